// round 11
// baseline (speedup 1.0000x reference)
#include <cuda_runtime.h>
#include <cuda_bf16.h>
#include <cstdint>

#define B_    16
#define S_    16
#define D_    4096
#define H_    32
#define KVH_  8
#define HD_   128
#define NREP_ 4
#define MAXS_ 4096
#define MROWS 256
#define KS    4        // K-split factor for projection GEMMs
#define NC    6144     // qkv unified output columns

__device__ float  g_q  [MROWS * D_];
__device__ float  g_kn [MROWS * KVH_ * HD_];
__device__ float  g_vn [MROWS * KVH_ * HD_];
__device__ float  g_ctx[MROWS * D_];
__device__ float  g_p  [KS][MROWS * NC];   // GEMM partials
__device__ float2 g_tab[S_ * 64];          // rope cos/sin [s][pp]

__device__ __forceinline__ unsigned f2tf(float x) {
    unsigned r; asm("cvt.rna.tf32.f32 %0, %1;" : "=r"(r) : "f"(x)); return r;
}
__device__ __forceinline__ void mma8(float* d, unsigned a0, unsigned a1, unsigned a2,
                                     unsigned a3, unsigned b0, unsigned b1) {
    asm volatile(
        "mma.sync.aligned.m16n8k8.row.col.f32.tf32.tf32.f32 "
        "{%0,%1,%2,%3}, {%4,%5,%6,%7}, {%8,%9}, {%0,%1,%2,%3};"
        : "+f"(d[0]), "+f"(d[1]), "+f"(d[2]), "+f"(d[3])
        : "r"(a0), "r"(a1), "r"(a2), "r"(a3), "r"(b0), "r"(b1));
}
__device__ __forceinline__ void mma16h(float* d, unsigned a0, unsigned a1, unsigned a2,
                                       unsigned a3, unsigned b0, unsigned b1) {
    asm volatile(
        "mma.sync.aligned.m16n8k16.row.col.f32.f16.f16.f32 "
        "{%0,%1,%2,%3}, {%4,%5,%6,%7}, {%8,%9}, {%0,%1,%2,%3};"
        : "+f"(d[0]), "+f"(d[1]), "+f"(d[2]), "+f"(d[3])
        : "r"(a0), "r"(a1), "r"(a2), "r"(a3), "r"(b0), "r"(b1));
}
__device__ __forceinline__ float ex2f(float x) {
    float r; asm("ex2.approx.f32 %0, %1;" : "=f"(r) : "f"(x)); return r;
}
__device__ __forceinline__ unsigned packh2(float lo, float hi) {
    unsigned d; asm("cvt.rn.f16x2.f32 %0, %1, %2;" : "=r"(d) : "f"(hi), "f"(lo)); return d;
}
__device__ __forceinline__ void cpa16(float* s, const float* g) {
    unsigned sa = (unsigned)__cvta_generic_to_shared(s);
    asm volatile("cp.async.cg.shared.global [%0], [%1], 16;" :: "r"(sa), "l"(g));
}
__device__ __forceinline__ void cp_commit() { asm volatile("cp.async.commit_group;"); }
template<int N> __device__ __forceinline__ void cp_wait() {
    asm volatile("cp.async.wait_group %0;" :: "n"(N));
}
#define GROUP_BAR(id) asm volatile("bar.sync %0, 128;" :: "r"(id) : "memory")

// ======================= rope table =======================
__global__ void rope_tab_kernel(const int* __restrict__ sp) {
    int idx = threadIdx.x;
    int s = idx >> 6, pp = idx & 63;
    double f = (double)(sp[0] + s) * exp(-9.210340371976184 * ((double)pp / 64.0));
    double cd, sd; sincos(f, &sd, &cd);
    g_tab[idx] = make_float2((float)cd, (float)sd);
}

// ======================= GEMM 128x128, K-split =======================
#define BM 128
#define BK 32
#define AST 36
#define BST 136
#define GEMM_SMEM_BYTES ((2*BM*AST + 2*BK*BST) * 4)

__device__ void gemm_tile(const float* __restrict__ A, int lda,
                          const float* __restrict__ W, int ldw,
                          float* __restrict__ C, int ldc,
                          int m0, int n0w, int n0c, int kbase, int KT)
{
    extern __shared__ float sm[];
    float* As0 = sm;
    float* As1 = sm + BM * AST;
    float* Bs0 = sm + 2 * BM * AST;
    float* Bs1 = sm + 2 * BM * AST + BK * BST;

    int tid = threadIdx.x, lane = tid & 31, wid = tid >> 5;
    int wm = wid >> 2, wn = wid & 3;
    int gr = lane >> 2, kq = lane & 3;

    float acc[4][4][4];
#pragma unroll
    for (int mt = 0; mt < 4; mt++)
#pragma unroll
        for (int nt = 0; nt < 4; nt++)
#pragma unroll
            for (int i = 0; i < 4; i++) acc[mt][nt][i] = 0.f;

    {
#pragma unroll
        for (int i = 0; i < 4; i++) {
            int idx = i * 256 + tid; int r = idx >> 3, c4 = idx & 7;
            cpa16(As0 + r * AST + c4 * 4, A + (long)(m0 + r) * lda + kbase + c4 * 4);
        }
#pragma unroll
        for (int i = 0; i < 4; i++) {
            int idx = i * 256 + tid; int r = idx >> 5, c4 = idx & 31;
            cpa16(Bs0 + r * BST + c4 * 4, W + (long)(kbase + r) * ldw + n0w + c4 * 4);
        }
        cp_commit();
    }

    for (int kt = 0; kt < KT; kt++) {
        float* Ab = (kt & 1) ? As1 : As0;
        float* Bb = (kt & 1) ? Bs1 : Bs0;
        if (kt + 1 < KT) {
            float* An = (kt & 1) ? As0 : As1;
            float* Bn = (kt & 1) ? Bs0 : Bs1;
            int k1 = kbase + (kt + 1) * BK;
#pragma unroll
            for (int i = 0; i < 4; i++) {
                int idx = i * 256 + tid; int r = idx >> 3, c4 = idx & 7;
                cpa16(An + r * AST + c4 * 4, A + (long)(m0 + r) * lda + k1 + c4 * 4);
            }
#pragma unroll
            for (int i = 0; i < 4; i++) {
                int idx = i * 256 + tid; int r = idx >> 5, c4 = idx & 31;
                cpa16(Bn + r * BST + c4 * 4, W + (long)(k1 + r) * ldw + n0w + c4 * 4);
            }
            cp_commit();
            cp_wait<1>();
        } else {
            cp_wait<0>();
        }
        __syncthreads();
#pragma unroll
        for (int kk = 0; kk < 4; kk++) {
            unsigned af[4][4], bf[4][2];
#pragma unroll
            for (int mt = 0; mt < 4; mt++) {
                int rm = wm * 64 + mt * 16;
                const float* p0 = Ab + (rm + gr) * AST + kk * 8 + kq;
                const float* p1 = Ab + (rm + gr + 8) * AST + kk * 8 + kq;
                af[mt][0] = f2tf(p0[0]); af[mt][1] = f2tf(p1[0]);
                af[mt][2] = f2tf(p0[4]); af[mt][3] = f2tf(p1[4]);
            }
#pragma unroll
            for (int nt = 0; nt < 4; nt++) {
                int cb = wn * 32 + nt * 8 + gr;
                bf[nt][0] = f2tf(Bb[(kk * 8 + kq) * BST + cb]);
                bf[nt][1] = f2tf(Bb[(kk * 8 + kq + 4) * BST + cb]);
            }
#pragma unroll
            for (int mt = 0; mt < 4; mt++)
#pragma unroll
                for (int nt = 0; nt < 4; nt++)
                    mma8(acc[mt][nt], af[mt][0], af[mt][1], af[mt][2], af[mt][3],
                         bf[nt][0], bf[nt][1]);
        }
        __syncthreads();
    }

#pragma unroll
    for (int mt = 0; mt < 4; mt++)
#pragma unroll
        for (int nt = 0; nt < 4; nt++) {
            int row = m0 + wm * 64 + mt * 16 + gr;
            int col = n0c + wn * 32 + nt * 8 + 2 * kq;
            *(float2*)(C + (long)row * ldc + col) =
                make_float2(acc[mt][nt][0], acc[mt][nt][1]);
            *(float2*)(C + (long)(row + 8) * ldc + col) =
                make_float2(acc[mt][nt][2], acc[mt][nt][3]);
        }
}

__global__ void qkv_kernel(const float* __restrict__ x, const float* __restrict__ Wq,
                           const float* __restrict__ Wk, const float* __restrict__ Wv) {
    int y = blockIdx.y, z = blockIdx.z;
    const float* W; int ldw, n0w, n0c;
    if (y < 32)      { W = Wq; ldw = 4096; n0w = y * 128;        n0c = y * 128; }
    else if (y < 40) { W = Wk; ldw = 1024; n0w = (y - 32) * 128; n0c = 4096 + (y - 32) * 128; }
    else             { W = Wv; ldw = 1024; n0w = (y - 40) * 128; n0c = 5120 + (y - 40) * 128; }
    gemm_tile(x, 4096, W, ldw, g_p[z], NC, blockIdx.x * BM, n0w, n0c, z * 1024, 32);
}

__global__ void out_kernel(const float* __restrict__ Wo) {
    int z = blockIdx.z;
    gemm_tile(g_ctx, 4096, Wo, 4096, g_p[z], 4096,
              blockIdx.x * BM, blockIdx.y * 128, blockIdx.y * 128, z * 1024, 32);
}

// ======================= combines =======================
__global__ void qkv_combine_kernel() {
    int idx = blockIdx.x * 256 + threadIdx.x;
    int row = idx / (NC / 2);
    int p   = idx - row * (NC / 2);
    int col = 2 * p;
    float v0 = 0.f, v1 = 0.f;
#pragma unroll
    for (int h = 0; h < KS; h++) {
        const float* src = g_p[h] + (long)row * NC + col;
        v0 += src[0]; v1 += src[1];
    }
    if (col < 4096) {
        int pp = (col & 127) >> 1;
        float2 cs = g_tab[((row & 15) << 6) + pp];
        // fold 1/sqrt(HD) * log2(e): scores land in base-2 domain
        const float qs = 0.08838834764831845f * 1.4426950408889634f;
        float t = (v0 * cs.x - v1 * cs.y) * qs;
        v1 = (v0 * cs.y + v1 * cs.x) * qs; v0 = t;
        *(float2*)(g_q + (long)row * 4096 + col) = make_float2(v0, v1);
    } else if (col < 5120) {
        int c2 = col - 4096;
        int pp = (c2 & 127) >> 1;
        float2 cs = g_tab[((row & 15) << 6) + pp];
        float t = v0 * cs.x - v1 * cs.y;
        v1 = v0 * cs.y + v1 * cs.x; v0 = t;
        *(float2*)(g_kn + (long)row * 1024 + c2) = make_float2(v0, v1);
    } else {
        *(float2*)(g_vn + (long)row * 1024 + (col - 5120)) = make_float2(v0, v1);
    }
}

__global__ void out_combine_kernel(float* __restrict__ out) {
    int idx = blockIdx.x * 256 + threadIdx.x;
    float4 a = *(const float4*)(g_p[0] + 4 * (long)idx);
    float4 b = *(const float4*)(g_p[1] + 4 * (long)idx);
    float4 c = *(const float4*)(g_p[2] + 4 * (long)idx);
    float4 d = *(const float4*)(g_p[3] + 4 * (long)idx);
    *(float4*)(out + 4 * (long)idx) =
        make_float4(a.x + b.x + c.x + d.x, a.y + b.y + c.y + d.y,
                    a.z + b.z + c.z + d.z, a.w + b.w + c.w + d.w);
}

// ======================= attention =======================
// 512 thr, TC=64, fp16 mma, permuted half2 layout (pi(o) = (o&3)*2 + (o>>2)
// within each 8-word group -> all fragment pairs adjacent -> LDS.64/STS.64),
// double-buffered Kh/Vh with convert(j+1) pipelined inside iteration j.
#define TC   64
#define KSTR 132
#define VSTR 132
#define KW   68     // half2 words per Kh row (64 d-pairs + pad)
#define VW   36     // half2 words per Vh row (32 t-pairs + pad)
#define PW   36     // half2 words per Ph row
#define KHSZ (TC * KW)
#define VHSZ (128 * VW)
#define AOFF_K0  0
#define AOFF_K1  (TC*KSTR)
#define AOFF_V0  (2*TC*KSTR)
#define AOFF_V1  (AOFF_V0 + TC*VSTR)
#define AOFF_KH  (AOFF_V1 + TC*VSTR)
#define AOFF_VH  (AOFF_KH + 2*KHSZ)
#define AOFF_PH  (AOFF_VH + 2*VHSZ)
#define AOFF_EX  (AOFF_PH + 64*PW)
#define ATTN_SMEM_BYTES ((AOFF_EX + 512) * 4)

__device__ __forceinline__ void attn_load_kv(
    const float* __restrict__ cache_k, const float* __restrict__ cache_v,
    int b, int kvh, int start, int kvlen, int t0, float* Ks, float* Vs, int tid)
{
#pragma unroll
    for (int i = 0; i < 4; i++) {
        int idx = i * 512 + tid; int r = idx >> 5, c4 = idx & 31;
        int t = t0 + r;
        const float *sk, *sv;
        if (t < start) {
            long o = ((((long)b * MAXS_ + t) * KVH_) + kvh) * HD_ + c4 * 4;
            sk = cache_k + o; sv = cache_v + o;
        } else {
            int tt = min(t, kvlen - 1);
            long o = (((long)(b * S_ + (tt - start))) * KVH_ + kvh) * HD_ + c4 * 4;
            sk = g_kn + o; sv = g_vn + o;
        }
        cpa16(Ks + r * KSTR + c4 * 4, sk);
        cpa16(Vs + r * VSTR + c4 * 4, sv);
    }
    cp_commit();
}

__global__ void __launch_bounds__(512, 1)
attn_kernel(const float* __restrict__ cache_k,
            const float* __restrict__ cache_v,
            const int* __restrict__ sp)
{
    extern __shared__ float sm[];
    float* Ksb[2] = { sm + AOFF_K0, sm + AOFF_K1 };
    float* Vsb[2] = { sm + AOFF_V0, sm + AOFF_V1 };
    unsigned* KhW = (unsigned*)(sm + AOFF_KH);
    unsigned* VhW = (unsigned*)(sm + AOFF_VH);
    unsigned* PhW = (unsigned*)(sm + AOFF_PH);
    float* ex = sm + AOFF_EX;

    int tid = threadIdx.x, lane = tid & 31, wid = tid >> 5;
    int b = blockIdx.x >> 3, kvh = blockIdx.x & 7;
    int start = sp[0], kvlen = start + S_;
    int wm = wid & 3, wn = wid >> 2;       // 4 m-groups x 4 n-groups
    int gr = lane >> 2, kq = lane & 3;
    int rm = wm * 16;
    int gtid = wm * 32 + lane;             // id within the 4-warp wn-group

    // ---- Q fragments packed fp16 once (g_q pre-scaled by 1/sqrt(HD)*log2e) ----
    unsigned qh[8][4];
    {
        int r0 = rm + gr, r1 = r0 + 8;
        const float* q0 = g_q + (long)(b * S_ + (r0 & 15)) * D_ + (kvh * NREP_ + (r0 >> 4)) * HD_;
        const float* q1 = g_q + (long)(b * S_ + (r1 & 15)) * D_ + (kvh * NREP_ + (r1 >> 4)) * HD_;
#pragma unroll
        for (int kb = 0; kb < 8; kb++) {
            int d0 = kb * 16 + 2 * kq;
            qh[kb][0] = packh2(q0[d0],     q0[d0 + 1]);
            qh[kb][1] = packh2(q1[d0],     q1[d0 + 1]);
            qh[kb][2] = packh2(q0[d0 + 8], q0[d0 + 9]);
            qh[kb][3] = packh2(q1[d0 + 8], q1[d0 + 9]);
        }
    }

    // convert chunk cj: fp32 staging -> permuted fp16 buffers (cj&1)
    auto do_convert = [&](int cj) {
        const float* Kb = Ksb[cj & 1];
        const float* Vb = Vsb[cj & 1];
        unsigned* Kh = KhW + (cj & 1) * KHSZ;
        unsigned* Vh = VhW + (cj & 1) * VHSZ;
        int tok = wn * 16 + (gtid & 15);
        int slot = gtid >> 4;                              // 0..7
        int ps = ((slot & 3) << 1) | (slot >> 2);          // pi(slot)
        const float* krow = Kb + tok * KSTR;
        unsigned* kdst = Kh + tok * KW;
#pragma unroll
        for (int i = 0; i < 8; i++) {
            float2 v = *(const float2*)(krow + 2 * (slot + 8 * i));
            kdst[i * 8 + ps] = packh2(v.x, v.y);
        }
        int d = wn * 32 + (gtid & 31);
        int psub = gtid >> 5;                              // 0..3
#pragma unroll
        for (int i = 0; i < 8; i++) {
            int p = psub * 8 + i;                          // t-pair
            int pp = psub * 8 + (((i & 3) << 1) | (i >> 2));
            Vh[d * VW + pp] = packh2(Vb[(2 * p) * VSTR + d],
                                     Vb[(2 * p + 1) * VSTR + d]);
        }
    };

    float m0r = -1e30f, m1r = -1e30f, l0r = 0.f, l1r = 0.f;
    float cacc[4][4];
#pragma unroll
    for (int nt = 0; nt < 4; nt++)
#pragma unroll
        for (int i = 0; i < 4; i++) cacc[nt][i] = 0.f;

    int NCH = (kvlen + TC - 1) / TC;
    attn_load_kv(cache_k, cache_v, b, kvh, start, kvlen, 0, Ksb[0], Vsb[0], tid);
    attn_load_kv(cache_k, cache_v, b, kvh, start, kvlen, TC, Ksb[1], Vsb[1], tid);
    cp_wait<1>();
    __syncthreads();
    do_convert(0);
    __syncthreads();

    for (int j = 0; j < NCH; j++) {
        // refill the fp32 buffer chunk j vacated (convert(j) ran last iter)
        if (j + 2 < NCH)
            attn_load_kv(cache_k, cache_v, b, kvh, start, kvlen,
                         (j + 2) * TC, Ksb[j & 1], Vsb[j & 1], tid);

        const unsigned* Kh = KhW + (j & 1) * KHSZ;
        const unsigned* Vh = VhW + (j & 1) * VHSZ;

        // ---- S = Q K^T (fp16): warp covers cols [wn*16, wn*16+16) ----
        float sacc[2][4];
#pragma unroll
        for (int nt = 0; nt < 2; nt++)
#pragma unroll
            for (int i = 0; i < 4; i++) sacc[nt][i] = 0.f;
#pragma unroll
        for (int kb = 0; kb < 8; kb++) {
#pragma unroll
            for (int nt = 0; nt < 2; nt++) {
                int cb = wn * 16 + nt * 8;
                uint2 bb = *(const uint2*)&Kh[(cb + gr) * KW + kb * 8 + 2 * kq];
                mma16h(sacc[nt], qh[kb][0], qh[kb][1], qh[kb][2], qh[kb][3],
                       bb.x, bb.y);
            }
        }

        if (j == NCH - 1 && (kvlen & (TC - 1))) {     // never taken for kvlen=4096
#pragma unroll
            for (int nt = 0; nt < 2; nt++) {
                int cb = j * TC + wn * 16 + nt * 8 + 2 * kq;
                if (cb >= kvlen)     { sacc[nt][0] = -1e30f; sacc[nt][2] = -1e30f; }
                if (cb + 1 >= kvlen) { sacc[nt][1] = -1e30f; sacc[nt][3] = -1e30f; }
            }
        }

        // ---- row max across 4 wn warps ----
        float mw0 = fmaxf(fmaxf(sacc[0][0], sacc[0][1]), fmaxf(sacc[1][0], sacc[1][1]));
        float mw1 = fmaxf(fmaxf(sacc[0][2], sacc[0][3]), fmaxf(sacc[1][2], sacc[1][3]));
        mw0 = fmaxf(mw0, __shfl_xor_sync(0xffffffffu, mw0, 1));
        mw0 = fmaxf(mw0, __shfl_xor_sync(0xffffffffu, mw0, 2));
        mw1 = fmaxf(mw1, __shfl_xor_sync(0xffffffffu, mw1, 1));
        mw1 = fmaxf(mw1, __shfl_xor_sync(0xffffffffu, mw1, 2));
        if (kq == 0) { ex[wn * 64 + rm + gr] = mw0; ex[wn * 64 + rm + gr + 8] = mw1; }
        GROUP_BAR(1 + wm);
        float M0 = m0r, M1 = m1r;
#pragma unroll
        for (int w = 0; w < 4; w++) {
            M0 = fmaxf(M0, ex[w * 64 + rm + gr]);
            M1 = fmaxf(M1, ex[w * 64 + rm + gr + 8]);
        }

        // ---- rescale on max-bump (l and O held to the same m history) ----
        if (M0 > m0r || M1 > m1r) {
            float sc0 = ex2f(m0r - M0), sc1 = ex2f(m1r - M1);
            l0r *= sc0;  l1r *= sc1;
#pragma unroll
            for (int nt = 0; nt < 4; nt++) {
                cacc[nt][0] *= sc0; cacc[nt][1] *= sc0;
                cacc[nt][2] *= sc1; cacc[nt][3] *= sc1;
            }
            m0r = M0;  m1r = M1;
        }

        // ---- p' = 2^(s-(M-8)); local l accumulation; P store (STS.64) ----
        float Mb0 = M0 - 8.f, Mb1 = M1 - 8.f;
        float e00 = ex2f(sacc[0][0] - Mb0), e01 = ex2f(sacc[0][1] - Mb0);
        float e10 = ex2f(sacc[1][0] - Mb0), e11 = ex2f(sacc[1][1] - Mb0);
        float f00 = ex2f(sacc[0][2] - Mb1), f01 = ex2f(sacc[0][3] - Mb1);
        float f10 = ex2f(sacc[1][2] - Mb1), f11 = ex2f(sacc[1][3] - Mb1);
        {
            int w0 = (rm + gr) * PW + wn * 8 + 2 * kq;
            *(uint2*)&PhW[w0]          = make_uint2(packh2(e00, e01), packh2(e10, e11));
            *(uint2*)&PhW[w0 + 8 * PW] = make_uint2(packh2(f00, f01), packh2(f10, f11));
        }
        l0r += (e00 + e01) + (e10 + e11);
        l1r += (f00 + f01) + (f10 + f11);
        GROUP_BAR(1 + wm);    // P rows of this wm group visible

        // ---- pipelined convert of chunk j+1 (data guaranteed by cp_wait) ----
        if (j + 1 < NCH) {
            if (j + 2 < NCH) { cp_wait<1>(); } else { cp_wait<0>(); }
            __syncthreads();             // cp.async data visible CTA-wide
            do_convert(j + 1);
        }

        // ---- O += P V (fp16): warp covers dims [wn*32, wn*32+32) ----
#pragma unroll
        for (int kb = 0; kb < 4; kb++) {
            uint2 aa0 = *(const uint2*)&PhW[(rm + gr) * PW + kb * 8 + 2 * kq];
            uint2 aa1 = *(const uint2*)&PhW[(rm + gr + 8) * PW + kb * 8 + 2 * kq];
#pragma unroll
            for (int nt = 0; nt < 4; nt++) {
                int dc = wn * 32 + nt * 8;
                uint2 bb = *(const uint2*)&Vh[(dc + gr) * VW + kb * 8 + 2 * kq];
                mma16h(cacc[nt], aa0.x, aa1.x, aa0.y, aa1.y, bb.x, bb.y);
            }
        }

        __syncthreads();   // Kh/Vh(j+1) + PhW reuse + fp32 buffer handoff
    }

    // ---- epilogue: reduce l across lanes and wn groups, normalize, write ----
    l0r += __shfl_xor_sync(0xffffffffu, l0r, 1);
    l0r += __shfl_xor_sync(0xffffffffu, l0r, 2);
    l1r += __shfl_xor_sync(0xffffffffu, l1r, 1);
    l1r += __shfl_xor_sync(0xffffffffu, l1r, 2);
    if (kq == 0) { ex[wn * 64 + rm + gr] = l0r; ex[wn * 64 + rm + gr + 8] = l1r; }
    GROUP_BAR(1 + wm);
    float L0 = 0.f, L1 = 0.f;
#pragma unroll
    for (int w = 0; w < 4; w++) {
        L0 += ex[w * 64 + rm + gr];
        L1 += ex[w * 64 + rm + gr + 8];
    }
    float inv0 = 1.f / L0, inv1 = 1.f / L1;
    int r0 = rm + gr, r1 = r0 + 8;
    long base0 = (long)(b * S_ + (r0 & 15)) * D_ + (kvh * NREP_ + (r0 >> 4)) * HD_;
    long base1 = (long)(b * S_ + (r1 & 15)) * D_ + (kvh * NREP_ + (r1 >> 4)) * HD_;
#pragma unroll
    for (int nt = 0; nt < 4; nt++) {
        int col = wn * 32 + nt * 8 + 2 * kq;
        *(float2*)(g_ctx + base0 + col) = make_float2(cacc[nt][0] * inv0, cacc[nt][1] * inv0);
        *(float2*)(g_ctx + base1 + col) = make_float2(cacc[nt][2] * inv1, cacc[nt][3] * inv1);
    }
}

// ======================= launch =======================
extern "C" void kernel_launch(void* const* d_in, const int* in_sizes, int n_in,
                              void* d_out, int out_size) {
    const float* x       = (const float*)d_in[0];
    const float* Wq      = (const float*)d_in[1];
    const float* Wk      = (const float*)d_in[2];
    const float* Wv      = (const float*)d_in[3];
    const float* Wo      = (const float*)d_in[4];
    const float* cache_k = (const float*)d_in[5];
    const float* cache_v = (const float*)d_in[6];
    const int*   sp      = (const int*)d_in[7];
    float* out = (float*)d_out;

    cudaFuncSetAttribute(qkv_kernel,  cudaFuncAttributeMaxDynamicSharedMemorySize, GEMM_SMEM_BYTES);
    cudaFuncSetAttribute(out_kernel,  cudaFuncAttributeMaxDynamicSharedMemorySize, GEMM_SMEM_BYTES);
    cudaFuncSetAttribute(attn_kernel, cudaFuncAttributeMaxDynamicSharedMemorySize, ATTN_SMEM_BYTES);

    rope_tab_kernel<<<1, 1024>>>(sp);
    qkv_kernel<<<dim3(2, 48, KS), 256, GEMM_SMEM_BYTES>>>(x, Wq, Wk, Wv);
    qkv_combine_kernel<<<(MROWS * NC / 2) / 256, 256>>>();
    attn_kernel<<<128, 512, ATTN_SMEM_BYTES>>>(cache_k, cache_v, sp);
    out_kernel<<<dim3(2, 32, KS), 256, GEMM_SMEM_BYTES>>>(Wo);
    out_combine_kernel<<<(MROWS * D_ / 4) / 256, 256>>>(out);
}

// round 12
// speedup vs baseline: 1.0507x; 1.0507x over previous
#include <cuda_runtime.h>
#include <cuda_bf16.h>
#include <cstdint>

#define B_    16
#define S_    16
#define D_    4096
#define H_    32
#define KVH_  8
#define HD_   128
#define NREP_ 4
#define MAXS_ 4096
#define MROWS 256
#define KS    4
#define NC    6144

__device__ float  g_q  [MROWS * D_];
__device__ float  g_kn [MROWS * KVH_ * HD_];
__device__ float  g_vn [MROWS * KVH_ * HD_];
__device__ float  g_ctx[MROWS * D_];
__device__ float  g_p  [KS][MROWS * NC];
__device__ float2 g_tab[S_ * 64];

__device__ __forceinline__ unsigned f2tf(float x) {
    unsigned r; asm("cvt.rna.tf32.f32 %0, %1;" : "=r"(r) : "f"(x)); return r;
}
__device__ __forceinline__ void mma8(float* d, unsigned a0, unsigned a1, unsigned a2,
                                     unsigned a3, unsigned b0, unsigned b1) {
    asm volatile(
        "mma.sync.aligned.m16n8k8.row.col.f32.tf32.tf32.f32 "
        "{%0,%1,%2,%3}, {%4,%5,%6,%7}, {%8,%9}, {%0,%1,%2,%3};"
        : "+f"(d[0]), "+f"(d[1]), "+f"(d[2]), "+f"(d[3])
        : "r"(a0), "r"(a1), "r"(a2), "r"(a3), "r"(b0), "r"(b1));
}
__device__ __forceinline__ void mma16h(float* d, unsigned a0, unsigned a1, unsigned a2,
                                       unsigned a3, unsigned b0, unsigned b1) {
    asm volatile(
        "mma.sync.aligned.m16n8k16.row.col.f32.f16.f16.f32 "
        "{%0,%1,%2,%3}, {%4,%5,%6,%7}, {%8,%9}, {%0,%1,%2,%3};"
        : "+f"(d[0]), "+f"(d[1]), "+f"(d[2]), "+f"(d[3])
        : "r"(a0), "r"(a1), "r"(a2), "r"(a3), "r"(b0), "r"(b1));
}
__device__ __forceinline__ float ex2f(float x) {
    float r; asm("ex2.approx.f32 %0, %1;" : "=f"(r) : "f"(x)); return r;
}
__device__ __forceinline__ unsigned packh2(float lo, float hi) {
    unsigned d; asm("cvt.rn.f16x2.f32 %0, %1, %2;" : "=r"(d) : "f"(hi), "f"(lo)); return d;
}
__device__ __forceinline__ void cpa16(float* s, const float* g) {
    unsigned sa = (unsigned)__cvta_generic_to_shared(s);
    asm volatile("cp.async.cg.shared.global [%0], [%1], 16;" :: "r"(sa), "l"(g));
}
__device__ __forceinline__ void cp_commit() { asm volatile("cp.async.commit_group;"); }
template<int N> __device__ __forceinline__ void cp_wait() {
    asm volatile("cp.async.wait_group %0;" :: "n"(N));
}
#define GROUP_BAR(id) asm volatile("bar.sync %0, 128;" :: "r"(id) : "memory")

// ======================= rope table =======================
__global__ void rope_tab_kernel(const int* __restrict__ sp) {
    int idx = threadIdx.x;
    int s = idx >> 6, pp = idx & 63;
    double f = (double)(sp[0] + s) * exp(-9.210340371976184 * ((double)pp / 64.0));
    double cd, sd; sincos(f, &sd, &cd);
    g_tab[idx] = make_float2((float)cd, (float)sd);
}

// ======================= GEMM 128x128, K-split (unchanged from R10) =======================
#define BM 128
#define BK 32
#define AST 36
#define BST 136
#define GEMM_SMEM_BYTES ((2*BM*AST + 2*BK*BST) * 4)

__device__ void gemm_tile(const float* __restrict__ A, int lda,
                          const float* __restrict__ W, int ldw,
                          float* __restrict__ C, int ldc,
                          int m0, int n0w, int n0c, int kbase, int KT)
{
    extern __shared__ float sm[];
    float* As0 = sm;
    float* As1 = sm + BM * AST;
    float* Bs0 = sm + 2 * BM * AST;
    float* Bs1 = sm + 2 * BM * AST + BK * BST;

    int tid = threadIdx.x, lane = tid & 31, wid = tid >> 5;
    int wm = wid >> 2, wn = wid & 3;
    int gr = lane >> 2, kq = lane & 3;

    float acc[4][4][4];
#pragma unroll
    for (int mt = 0; mt < 4; mt++)
#pragma unroll
        for (int nt = 0; nt < 4; nt++)
#pragma unroll
            for (int i = 0; i < 4; i++) acc[mt][nt][i] = 0.f;

    {
#pragma unroll
        for (int i = 0; i < 4; i++) {
            int idx = i * 256 + tid; int r = idx >> 3, c4 = idx & 7;
            cpa16(As0 + r * AST + c4 * 4, A + (long)(m0 + r) * lda + kbase + c4 * 4);
        }
#pragma unroll
        for (int i = 0; i < 4; i++) {
            int idx = i * 256 + tid; int r = idx >> 5, c4 = idx & 31;
            cpa16(Bs0 + r * BST + c4 * 4, W + (long)(kbase + r) * ldw + n0w + c4 * 4);
        }
        cp_commit();
    }

    for (int kt = 0; kt < KT; kt++) {
        float* Ab = (kt & 1) ? As1 : As0;
        float* Bb = (kt & 1) ? Bs1 : Bs0;
        if (kt + 1 < KT) {
            float* An = (kt & 1) ? As0 : As1;
            float* Bn = (kt & 1) ? Bs0 : Bs1;
            int k1 = kbase + (kt + 1) * BK;
#pragma unroll
            for (int i = 0; i < 4; i++) {
                int idx = i * 256 + tid; int r = idx >> 3, c4 = idx & 7;
                cpa16(An + r * AST + c4 * 4, A + (long)(m0 + r) * lda + k1 + c4 * 4);
            }
#pragma unroll
            for (int i = 0; i < 4; i++) {
                int idx = i * 256 + tid; int r = idx >> 5, c4 = idx & 31;
                cpa16(Bn + r * BST + c4 * 4, W + (long)(k1 + r) * ldw + n0w + c4 * 4);
            }
            cp_commit();
            cp_wait<1>();
        } else {
            cp_wait<0>();
        }
        __syncthreads();
#pragma unroll
        for (int kk = 0; kk < 4; kk++) {
            unsigned af[4][4], bf[4][2];
#pragma unroll
            for (int mt = 0; mt < 4; mt++) {
                int rm = wm * 64 + mt * 16;
                const float* p0 = Ab + (rm + gr) * AST + kk * 8 + kq;
                const float* p1 = Ab + (rm + gr + 8) * AST + kk * 8 + kq;
                af[mt][0] = f2tf(p0[0]); af[mt][1] = f2tf(p1[0]);
                af[mt][2] = f2tf(p0[4]); af[mt][3] = f2tf(p1[4]);
            }
#pragma unroll
            for (int nt = 0; nt < 4; nt++) {
                int cb = wn * 32 + nt * 8 + gr;
                bf[nt][0] = f2tf(Bb[(kk * 8 + kq) * BST + cb]);
                bf[nt][1] = f2tf(Bb[(kk * 8 + kq + 4) * BST + cb]);
            }
#pragma unroll
            for (int mt = 0; mt < 4; mt++)
#pragma unroll
                for (int nt = 0; nt < 4; nt++)
                    mma8(acc[mt][nt], af[mt][0], af[mt][1], af[mt][2], af[mt][3],
                         bf[nt][0], bf[nt][1]);
        }
        __syncthreads();
    }

#pragma unroll
    for (int mt = 0; mt < 4; mt++)
#pragma unroll
        for (int nt = 0; nt < 4; nt++) {
            int row = m0 + wm * 64 + mt * 16 + gr;
            int col = n0c + wn * 32 + nt * 8 + 2 * kq;
            *(float2*)(C + (long)row * ldc + col) =
                make_float2(acc[mt][nt][0], acc[mt][nt][1]);
            *(float2*)(C + (long)(row + 8) * ldc + col) =
                make_float2(acc[mt][nt][2], acc[mt][nt][3]);
        }
}

__global__ void qkv_kernel(const float* __restrict__ x, const float* __restrict__ Wq,
                           const float* __restrict__ Wk, const float* __restrict__ Wv) {
    int y = blockIdx.y, z = blockIdx.z;
    const float* W; int ldw, n0w, n0c;
    if (y < 32)      { W = Wq; ldw = 4096; n0w = y * 128;        n0c = y * 128; }
    else if (y < 40) { W = Wk; ldw = 1024; n0w = (y - 32) * 128; n0c = 4096 + (y - 32) * 128; }
    else             { W = Wv; ldw = 1024; n0w = (y - 40) * 128; n0c = 5120 + (y - 40) * 128; }
    gemm_tile(x, 4096, W, ldw, g_p[z], NC, blockIdx.x * BM, n0w, n0c, z * 1024, 32);
}

__global__ void out_kernel(const float* __restrict__ Wo) {
    int z = blockIdx.z;
    gemm_tile(g_ctx, 4096, Wo, 4096, g_p[z], 4096,
              blockIdx.x * BM, blockIdx.y * 128, blockIdx.y * 128, z * 1024, 32);
}

// ======================= combines =======================
__global__ void qkv_combine_kernel() {
    int idx = blockIdx.x * 256 + threadIdx.x;
    int row = idx / (NC / 2);
    int p   = idx - row * (NC / 2);
    int col = 2 * p;
    float v0 = 0.f, v1 = 0.f;
#pragma unroll
    for (int h = 0; h < KS; h++) {
        const float* src = g_p[h] + (long)row * NC + col;
        v0 += src[0]; v1 += src[1];
    }
    if (col < 4096) {
        int pp = (col & 127) >> 1;
        float2 cs = g_tab[((row & 15) << 6) + pp];
        const float qs = 0.08838834764831845f * 1.4426950408889634f;
        float t = (v0 * cs.x - v1 * cs.y) * qs;
        v1 = (v0 * cs.y + v1 * cs.x) * qs; v0 = t;
        *(float2*)(g_q + (long)row * 4096 + col) = make_float2(v0, v1);
    } else if (col < 5120) {
        int c2 = col - 4096;
        int pp = (c2 & 127) >> 1;
        float2 cs = g_tab[((row & 15) << 6) + pp];
        float t = v0 * cs.x - v1 * cs.y;
        v1 = v0 * cs.y + v1 * cs.x; v0 = t;
        *(float2*)(g_kn + (long)row * 1024 + c2) = make_float2(v0, v1);
    } else {
        *(float2*)(g_vn + (long)row * 1024 + (col - 5120)) = make_float2(v0, v1);
    }
}

__global__ void out_combine_kernel(float* __restrict__ out) {
    int idx = blockIdx.x * 256 + threadIdx.x;
    float4 a = *(const float4*)(g_p[0] + 4 * (long)idx);
    float4 b = *(const float4*)(g_p[1] + 4 * (long)idx);
    float4 c = *(const float4*)(g_p[2] + 4 * (long)idx);
    float4 d = *(const float4*)(g_p[3] + 4 * (long)idx);
    *(float4*)(out + 4 * (long)idx) =
        make_float4(a.x + b.x + c.x + d.x, a.y + b.y + c.y + d.y,
                    a.z + b.z + c.z + d.z, a.w + b.w + c.w + d.w);
}

// ======================= attention: 4 decoupled token-group pipelines =======================
// 512 thr = 4 wm x 4 wn warps. Group wn owns tokens [wn*16, wn*16+16) of every
// chunk: loads, converts, QK^T, register-P, PV over its tokens x all 128 dims,
// with per-group (m,l,O). No CTA-wide sync in the loop; exact merge in epilogue.
#define TC   64
#define SSTR 132    // fp32 staging stride
#define KW   68     // Kh: 64 tokens x 64 d-pairs (+4 pad)
#define VW   36     // Vh: 128 dims x 32 t-pairs (+4 pad)
#define QW   68     // Qh: 64 rows x 64 d-pairs (+4 pad)
#define AOFF_K0  0
#define AOFF_K1  (TC*SSTR)
#define AOFF_V0  (2*TC*SSTR)
#define AOFF_V1  (3*TC*SSTR)
#define AOFF_KH  (4*TC*SSTR)
#define AOFF_VH  (AOFF_KH + TC*KW)
#define AOFF_QH  (AOFF_VH + 128*VW)
#define AOFF_EX  (AOFF_QH + 64*QW)
#define ATTN_SMEM_BYTES ((AOFF_EX + 512) * 4)
#define OBS  (TC*SSTR)   // per-group O-partial block in reused staging (8448 floats)

__device__ __forceinline__ void attn_load_kv2(
    const float* __restrict__ cache_k, const float* __restrict__ cache_v,
    int b, int kvh, int start, int kvlen, int t0, float* Ks, float* Vs,
    int wn, int gtid)
{
    int r = wn * 16 + (gtid >> 3);      // group's own token rows
    int c0 = (gtid & 7) * 4;
    int t = t0 + r;
    const float *sk, *sv;
    if (t < start) {
        long o = ((((long)b * MAXS_ + t) * KVH_) + kvh) * HD_;
        sk = cache_k + o; sv = cache_v + o;
    } else {
        int tt = min(t, kvlen - 1);
        long o = (((long)(b * S_ + (tt - start))) * KVH_ + kvh) * HD_;
        sk = g_kn + o; sv = g_vn + o;
    }
#pragma unroll
    for (int i = 0; i < 4; i++) {
        cpa16(Ks + r * SSTR + (c0 + i) * 4, sk + (c0 + i) * 4);
        cpa16(Vs + r * SSTR + (c0 + i) * 4, sv + (c0 + i) * 4);
    }
    cp_commit();
}

__global__ void __launch_bounds__(512, 1)
attn_kernel(const float* __restrict__ cache_k,
            const float* __restrict__ cache_v,
            const int* __restrict__ sp)
{
    extern __shared__ float sm[];
    float* KsB[2] = { sm + AOFF_K0, sm + AOFF_K1 };
    float* VsB[2] = { sm + AOFF_V0, sm + AOFF_V1 };
    unsigned* Kh = (unsigned*)(sm + AOFF_KH);
    unsigned* Vh = (unsigned*)(sm + AOFF_VH);
    unsigned* Qh = (unsigned*)(sm + AOFF_QH);
    float* ex = sm + AOFF_EX;     // [0:256) m, [256:512) scaled l

    int tid = threadIdx.x, lane = tid & 31, wid = tid >> 5;
    int b = blockIdx.x >> 3, kvh = blockIdx.x & 7;
    int start = sp[0], kvlen = start + S_;
    int wm = wid & 3, wn = wid >> 2;
    int gr = lane >> 2, kq = lane & 3;
    int rm = wm * 16;
    int gtid = wm * 32 + lane;           // id within group (0..127)

    // ---- Qh fill (fp16, once; g_q pre-scaled by 1/sqrt(HD)*log2e) ----
    {
        int r = tid >> 3, slot = tid & 7;
        const float* qp = g_q + (long)(b * S_ + (r & 15)) * D_ + (kvh * NREP_ + (r >> 4)) * HD_;
#pragma unroll
        for (int i = 0; i < 8; i++) {
            int w = slot + 8 * i;
            float2 v = *(const float2*)(qp + 2 * w);
            Qh[r * QW + w] = packh2(v.x, v.y);
        }
    }

    float m0r = -1e30f, m1r = -1e30f, l0r = 0.f, l1r = 0.f;
    float cacc[16][4];
#pragma unroll
    for (int nt = 0; nt < 16; nt++)
#pragma unroll
        for (int i = 0; i < 4; i++) cacc[nt][i] = 0.f;

    int NCH = (kvlen + TC - 1) / TC;
    attn_load_kv2(cache_k, cache_v, b, kvh, start, kvlen, 0,  KsB[0], VsB[0], wn, gtid);
    attn_load_kv2(cache_k, cache_v, b, kvh, start, kvlen, TC, KsB[1], VsB[1], wn, gtid);
    cp_wait<1>();
    __syncthreads();    // Qh + staging(0) visible

    for (int j = 0; j < NCH; j++) {
        const float* Ks = KsB[j & 1];
        const float* Vs = VsB[j & 1];

        // ---- convert own tokens: K [tok][d-pair], V transposed [d][t-pair] ----
        {
            int tok = wn * 16 + (gtid >> 3), slot = gtid & 7;
            const float* kr = Ks + tok * SSTR;
            unsigned* kd = Kh + tok * KW;
#pragma unroll
            for (int i = 0; i < 8; i++) {
                int w = slot + 8 * i;
                float2 v = *(const float2*)(kr + 2 * w);
                kd[w] = packh2(v.x, v.y);
            }
            int d = gtid;
#pragma unroll
            for (int i = 0; i < 8; i++) {
                int pl = wn * 8 + i;
                Vh[d * VW + pl] = packh2(Vs[(2 * pl) * SSTR + d],
                                         Vs[(2 * pl + 1) * SSTR + d]);
            }
        }
        GROUP_BAR(1 + wn);   // converts visible; staging reads done -> refill safe

        if (j + 2 < NCH)
            attn_load_kv2(cache_k, cache_v, b, kvh, start, kvlen,
                          (j + 2) * TC, KsB[j & 1], VsB[j & 1], wn, gtid);

        // ---- S = Q K^T over own 16 tokens ----
        float sacc[2][4];
#pragma unroll
        for (int nt = 0; nt < 2; nt++)
#pragma unroll
            for (int i = 0; i < 4; i++) sacc[nt][i] = 0.f;
#pragma unroll
        for (int kb = 0; kb < 8; kb++) {
            unsigned a0 = Qh[(rm + gr) * QW + kb * 8 + kq];
            unsigned a1 = Qh[(rm + gr + 8) * QW + kb * 8 + kq];
            unsigned a2 = Qh[(rm + gr) * QW + kb * 8 + kq + 4];
            unsigned a3 = Qh[(rm + gr + 8) * QW + kb * 8 + kq + 4];
#pragma unroll
            for (int nt = 0; nt < 2; nt++) {
                int cb = wn * 16 + nt * 8;
                unsigned b0 = Kh[(cb + gr) * KW + kb * 8 + kq];
                unsigned b1 = Kh[(cb + gr) * KW + kb * 8 + kq + 4];
                mma16h(sacc[nt], a0, a1, a2, a3, b0, b1);
            }
        }

        if (j == NCH - 1 && (kvlen & (TC - 1))) {   // never for kvlen=4096
#pragma unroll
            for (int nt = 0; nt < 2; nt++) {
                int tk = j * TC + wn * 16 + nt * 8 + 2 * kq;
                if (tk >= kvlen)     { sacc[nt][0] = -1e30f; sacc[nt][2] = -1e30f; }
                if (tk + 1 >= kvlen) { sacc[nt][1] = -1e30f; sacc[nt][3] = -1e30f; }
            }
        }

        // ---- warp-local online softmax (rows gr / gr+8) ----
        float mw0 = fmaxf(fmaxf(sacc[0][0], sacc[0][1]), fmaxf(sacc[1][0], sacc[1][1]));
        float mw1 = fmaxf(fmaxf(sacc[0][2], sacc[0][3]), fmaxf(sacc[1][2], sacc[1][3]));
        mw0 = fmaxf(mw0, __shfl_xor_sync(0xffffffffu, mw0, 1));
        mw0 = fmaxf(mw0, __shfl_xor_sync(0xffffffffu, mw0, 2));
        mw1 = fmaxf(mw1, __shfl_xor_sync(0xffffffffu, mw1, 1));
        mw1 = fmaxf(mw1, __shfl_xor_sync(0xffffffffu, mw1, 2));
        float M0 = fmaxf(m0r, mw0), M1 = fmaxf(m1r, mw1);
        if (__any_sync(0xffffffffu, (M0 > m0r) | (M1 > m1r))) {
            float sc0 = ex2f(m0r - M0), sc1 = ex2f(m1r - M1);
            l0r *= sc0;  l1r *= sc1;
#pragma unroll
            for (int nt = 0; nt < 16; nt++) {
                cacc[nt][0] *= sc0; cacc[nt][1] *= sc0;
                cacc[nt][2] *= sc1; cacc[nt][3] *= sc1;
            }
            m0r = M0;  m1r = M1;
        }
        float Mb0 = M0 - 8.f, Mb1 = M1 - 8.f;
        float g00 = ex2f(sacc[0][0] - Mb0), g01 = ex2f(sacc[0][1] - Mb0);
        float g02 = ex2f(sacc[0][2] - Mb1), g03 = ex2f(sacc[0][3] - Mb1);
        float h00 = ex2f(sacc[1][0] - Mb0), h01 = ex2f(sacc[1][1] - Mb0);
        float h02 = ex2f(sacc[1][2] - Mb1), h03 = ex2f(sacc[1][3] - Mb1);
        l0r += (g00 + g01) + (h00 + h01);
        l1r += (g02 + g03) + (h02 + h03);
        unsigned pa0 = packh2(g00, g01), pa1 = packh2(g02, g03);
        unsigned pa2 = packh2(h00, h01), pa3 = packh2(h02, h03);

        // ---- O += P V over own 16 tokens, all 128 dims (P in registers) ----
#pragma unroll
        for (int nt = 0; nt < 16; nt++) {
            unsigned b0 = Vh[(nt * 8 + gr) * VW + wn * 8 + kq];
            unsigned b1 = Vh[(nt * 8 + gr) * VW + wn * 8 + kq + 4];
            mma16h(cacc[nt], pa0, pa1, pa2, pa3, b0, b1);
        }

        if (j + 1 < NCH) { if (j + 2 < NCH) { cp_wait<1>(); } else { cp_wait<0>(); } }
        GROUP_BAR(1 + wn);   // Kh/Vh reads done; staging(j+1) visible group-wide
    }

    // ---- epilogue: exact merge of the 4 group-partials ----
    l0r += __shfl_xor_sync(0xffffffffu, l0r, 1);
    l0r += __shfl_xor_sync(0xffffffffu, l0r, 2);
    l1r += __shfl_xor_sync(0xffffffffu, l1r, 1);
    l1r += __shfl_xor_sync(0xffffffffu, l1r, 2);
    if (kq == 0) { ex[wn * 64 + rm + gr] = m0r; ex[wn * 64 + rm + gr + 8] = m1r; }
    __syncthreads();         // all loop reads of staging done; m visible
    float M0 = -1e30f, M1 = -1e30f;
#pragma unroll
    for (int w = 0; w < 4; w++) {
        M0 = fmaxf(M0, ex[w * 64 + rm + gr]);
        M1 = fmaxf(M1, ex[w * 64 + rm + gr + 8]);
    }
    float sc0 = ex2f(m0r - M0), sc1 = ex2f(m1r - M1);
    if (kq == 0) {
        ex[256 + wn * 64 + rm + gr]     = l0r * sc0;
        ex[256 + wn * 64 + rm + gr + 8] = l1r * sc1;
    }
    float* Ob = sm + wn * OBS;          // staging region reused: [4][64][SSTR]
#pragma unroll
    for (int nt = 0; nt < 16; nt++) {
        int d = nt * 8 + 2 * kq;
        *(float2*)&Ob[(rm + gr) * SSTR + d] =
            make_float2(cacc[nt][0] * sc0, cacc[nt][1] * sc0);
        *(float2*)&Ob[(rm + gr + 8) * SSTR + d] =
            make_float2(cacc[nt][2] * sc1, cacc[nt][3] * sc1);
    }
    __syncthreads();
#pragma unroll
    for (int i = 0; i < 4; i++) {
        int f = i * 512 + tid;
        int r = f >> 5, d4 = f & 31;
        float4 s0 = *(const float4*)&sm[0 * OBS + r * SSTR + d4 * 4];
        float4 s1 = *(const float4*)&sm[1 * OBS + r * SSTR + d4 * 4];
        float4 s2 = *(const float4*)&sm[2 * OBS + r * SSTR + d4 * 4];
        float4 s3 = *(const float4*)&sm[3 * OBS + r * SSTR + d4 * 4];
        float L = ex[256 + r] + ex[256 + 64 + r] + ex[256 + 128 + r] + ex[256 + 192 + r];
        float inv = 1.f / L;
        float4 o = make_float4((s0.x + s1.x + s2.x + s3.x) * inv,
                               (s0.y + s1.y + s2.y + s3.y) * inv,
                               (s0.z + s1.z + s2.z + s3.z) * inv,
                               (s0.w + s1.w + s2.w + s3.w) * inv);
        *(float4*)(g_ctx + (long)(b * S_ + (r & 15)) * D_ +
                   (kvh * NREP_ + (r >> 4)) * HD_ + d4 * 4) = o;
    }
}

// ======================= launch =======================
extern "C" void kernel_launch(void* const* d_in, const int* in_sizes, int n_in,
                              void* d_out, int out_size) {
    const float* x       = (const float*)d_in[0];
    const float* Wq      = (const float*)d_in[1];
    const float* Wk      = (const float*)d_in[2];
    const float* Wv      = (const float*)d_in[3];
    const float* Wo      = (const float*)d_in[4];
    const float* cache_k = (const float*)d_in[5];
    const float* cache_v = (const float*)d_in[6];
    const int*   sp      = (const int*)d_in[7];
    float* out = (float*)d_out;

    cudaFuncSetAttribute(qkv_kernel,  cudaFuncAttributeMaxDynamicSharedMemorySize, GEMM_SMEM_BYTES);
    cudaFuncSetAttribute(out_kernel,  cudaFuncAttributeMaxDynamicSharedMemorySize, GEMM_SMEM_BYTES);
    cudaFuncSetAttribute(attn_kernel, cudaFuncAttributeMaxDynamicSharedMemorySize, ATTN_SMEM_BYTES);

    rope_tab_kernel<<<1, 1024>>>(sp);
    qkv_kernel<<<dim3(2, 48, KS), 256, GEMM_SMEM_BYTES>>>(x, Wq, Wk, Wv);
    qkv_combine_kernel<<<(MROWS * NC / 2) / 256, 256>>>();
    attn_kernel<<<128, 512, ATTN_SMEM_BYTES>>>(cache_k, cache_v, sp);
    out_kernel<<<dim3(2, 32, KS), 256, GEMM_SMEM_BYTES>>>(Wo);
    out_combine_kernel<<<(MROWS * D_ / 4) / 256, 256>>>(out);
}

// round 13
// speedup vs baseline: 1.0616x; 1.0103x over previous
#include <cuda_runtime.h>
#include <cuda_bf16.h>
#include <cstdint>

#define B_    16
#define S_    16
#define D_    4096
#define H_    32
#define KVH_  8
#define HD_   128
#define NREP_ 4
#define MAXS_ 4096
#define MROWS 256
#define KS    4
#define NC    6144

__device__ float  g_q  [MROWS * D_];
__device__ float  g_kn [MROWS * KVH_ * HD_];
__device__ float  g_vn [MROWS * KVH_ * HD_];
__device__ float  g_ctx[MROWS * D_];
__device__ float  g_p  [KS][MROWS * NC];
__device__ float2 g_tab[S_ * 64];

__device__ __forceinline__ unsigned f2tf(float x) {
    unsigned r; asm("cvt.rna.tf32.f32 %0, %1;" : "=r"(r) : "f"(x)); return r;
}
__device__ __forceinline__ void mma8(float* d, unsigned a0, unsigned a1, unsigned a2,
                                     unsigned a3, unsigned b0, unsigned b1) {
    asm volatile(
        "mma.sync.aligned.m16n8k8.row.col.f32.tf32.tf32.f32 "
        "{%0,%1,%2,%3}, {%4,%5,%6,%7}, {%8,%9}, {%0,%1,%2,%3};"
        : "+f"(d[0]), "+f"(d[1]), "+f"(d[2]), "+f"(d[3])
        : "r"(a0), "r"(a1), "r"(a2), "r"(a3), "r"(b0), "r"(b1));
}
__device__ __forceinline__ void mma16h(float* d, unsigned a0, unsigned a1, unsigned a2,
                                       unsigned a3, unsigned b0, unsigned b1) {
    asm volatile(
        "mma.sync.aligned.m16n8k16.row.col.f32.f16.f16.f32 "
        "{%0,%1,%2,%3}, {%4,%5,%6,%7}, {%8,%9}, {%0,%1,%2,%3};"
        : "+f"(d[0]), "+f"(d[1]), "+f"(d[2]), "+f"(d[3])
        : "r"(a0), "r"(a1), "r"(a2), "r"(a3), "r"(b0), "r"(b1));
}
__device__ __forceinline__ void ldsm4(unsigned& r0, unsigned& r1, unsigned& r2,
                                      unsigned& r3, unsigned addr) {
    asm volatile("ldmatrix.sync.aligned.m8n8.x4.shared.b16 {%0,%1,%2,%3}, [%4];"
                 : "=r"(r0), "=r"(r1), "=r"(r2), "=r"(r3) : "r"(addr));
}
__device__ __forceinline__ float ex2f(float x) {
    float r; asm("ex2.approx.f32 %0, %1;" : "=f"(r) : "f"(x)); return r;
}
__device__ __forceinline__ unsigned packh2(float lo, float hi) {
    unsigned d; asm("cvt.rn.f16x2.f32 %0, %1, %2;" : "=r"(d) : "f"(hi), "f"(lo)); return d;
}
__device__ __forceinline__ void cpa16(float* s, const float* g) {
    unsigned sa = (unsigned)__cvta_generic_to_shared(s);
    asm volatile("cp.async.cg.shared.global [%0], [%1], 16;" :: "r"(sa), "l"(g));
}
__device__ __forceinline__ void cp_commit() { asm volatile("cp.async.commit_group;"); }
template<int N> __device__ __forceinline__ void cp_wait() {
    asm volatile("cp.async.wait_group %0;" :: "n"(N));
}
#define GROUP_BAR(id) asm volatile("bar.sync %0, 128;" :: "r"(id) : "memory")

// ======================= rope table =======================
__global__ void rope_tab_kernel(const int* __restrict__ sp) {
    int idx = threadIdx.x;
    int s = idx >> 6, pp = idx & 63;
    double f = (double)(sp[0] + s) * exp(-9.210340371976184 * ((double)pp / 64.0));
    double cd, sd; sincos(f, &sd, &cd);
    g_tab[idx] = make_float2((float)cd, (float)sd);
}

// ======================= GEMM 128x128, K-split =======================
#define BM 128
#define BK 32
#define AST 36
#define BST 136
#define GEMM_SMEM_BYTES ((2*BM*AST + 2*BK*BST) * 4)

__device__ void gemm_tile(const float* __restrict__ A, int lda,
                          const float* __restrict__ W, int ldw,
                          float* __restrict__ C, int ldc,
                          int m0, int n0w, int n0c, int kbase, int KT)
{
    extern __shared__ float sm[];
    float* As0 = sm;
    float* As1 = sm + BM * AST;
    float* Bs0 = sm + 2 * BM * AST;
    float* Bs1 = sm + 2 * BM * AST + BK * BST;

    int tid = threadIdx.x, lane = tid & 31, wid = tid >> 5;
    int wm = wid >> 2, wn = wid & 3;
    int gr = lane >> 2, kq = lane & 3;

    float acc[4][4][4];
#pragma unroll
    for (int mt = 0; mt < 4; mt++)
#pragma unroll
        for (int nt = 0; nt < 4; nt++)
#pragma unroll
            for (int i = 0; i < 4; i++) acc[mt][nt][i] = 0.f;

    {
#pragma unroll
        for (int i = 0; i < 4; i++) {
            int idx = i * 256 + tid; int r = idx >> 3, c4 = idx & 7;
            cpa16(As0 + r * AST + c4 * 4, A + (long)(m0 + r) * lda + kbase + c4 * 4);
        }
#pragma unroll
        for (int i = 0; i < 4; i++) {
            int idx = i * 256 + tid; int r = idx >> 5, c4 = idx & 31;
            cpa16(Bs0 + r * BST + c4 * 4, W + (long)(kbase + r) * ldw + n0w + c4 * 4);
        }
        cp_commit();
    }

    for (int kt = 0; kt < KT; kt++) {
        float* Ab = (kt & 1) ? As1 : As0;
        float* Bb = (kt & 1) ? Bs1 : Bs0;
        if (kt + 1 < KT) {
            float* An = (kt & 1) ? As0 : As1;
            float* Bn = (kt & 1) ? Bs0 : Bs1;
            int k1 = kbase + (kt + 1) * BK;
#pragma unroll
            for (int i = 0; i < 4; i++) {
                int idx = i * 256 + tid; int r = idx >> 3, c4 = idx & 7;
                cpa16(An + r * AST + c4 * 4, A + (long)(m0 + r) * lda + k1 + c4 * 4);
            }
#pragma unroll
            for (int i = 0; i < 4; i++) {
                int idx = i * 256 + tid; int r = idx >> 5, c4 = idx & 31;
                cpa16(Bn + r * BST + c4 * 4, W + (long)(k1 + r) * ldw + n0w + c4 * 4);
            }
            cp_commit();
            cp_wait<1>();
        } else {
            cp_wait<0>();
        }
        __syncthreads();
#pragma unroll
        for (int kk = 0; kk < 4; kk++) {
            unsigned af[4][4], bf[4][2];
#pragma unroll
            for (int mt = 0; mt < 4; mt++) {
                int rm = wm * 64 + mt * 16;
                const float* p0 = Ab + (rm + gr) * AST + kk * 8 + kq;
                const float* p1 = Ab + (rm + gr + 8) * AST + kk * 8 + kq;
                af[mt][0] = f2tf(p0[0]); af[mt][1] = f2tf(p1[0]);
                af[mt][2] = f2tf(p0[4]); af[mt][3] = f2tf(p1[4]);
            }
#pragma unroll
            for (int nt = 0; nt < 4; nt++) {
                int cb = wn * 32 + nt * 8 + gr;
                bf[nt][0] = f2tf(Bb[(kk * 8 + kq) * BST + cb]);
                bf[nt][1] = f2tf(Bb[(kk * 8 + kq + 4) * BST + cb]);
            }
#pragma unroll
            for (int mt = 0; mt < 4; mt++)
#pragma unroll
                for (int nt = 0; nt < 4; nt++)
                    mma8(acc[mt][nt], af[mt][0], af[mt][1], af[mt][2], af[mt][3],
                         bf[nt][0], bf[nt][1]);
        }
        __syncthreads();
    }

#pragma unroll
    for (int mt = 0; mt < 4; mt++)
#pragma unroll
        for (int nt = 0; nt < 4; nt++) {
            int row = m0 + wm * 64 + mt * 16 + gr;
            int col = n0c + wn * 32 + nt * 8 + 2 * kq;
            *(float2*)(C + (long)row * ldc + col) =
                make_float2(acc[mt][nt][0], acc[mt][nt][1]);
            *(float2*)(C + (long)(row + 8) * ldc + col) =
                make_float2(acc[mt][nt][2], acc[mt][nt][3]);
        }
}

__global__ void qkv_kernel(const float* __restrict__ x, const float* __restrict__ Wq,
                           const float* __restrict__ Wk, const float* __restrict__ Wv) {
    int y = blockIdx.y, z = blockIdx.z;
    const float* W; int ldw, n0w, n0c;
    if (y < 32)      { W = Wq; ldw = 4096; n0w = y * 128;        n0c = y * 128; }
    else if (y < 40) { W = Wk; ldw = 1024; n0w = (y - 32) * 128; n0c = 4096 + (y - 32) * 128; }
    else             { W = Wv; ldw = 1024; n0w = (y - 40) * 128; n0c = 5120 + (y - 40) * 128; }
    gemm_tile(x, 4096, W, ldw, g_p[z], NC, blockIdx.x * BM, n0w, n0c, z * 1024, 32);
}

__global__ void out_kernel(const float* __restrict__ Wo) {
    int z = blockIdx.z;
    gemm_tile(g_ctx, 4096, Wo, 4096, g_p[z], 4096,
              blockIdx.x * BM, blockIdx.y * 128, blockIdx.y * 128, z * 1024, 32);
}

// ======================= combines =======================
__global__ void qkv_combine_kernel() {
    int idx = blockIdx.x * 256 + threadIdx.x;
    int row = idx / (NC / 2);
    int p   = idx - row * (NC / 2);
    int col = 2 * p;
    float v0 = 0.f, v1 = 0.f;
#pragma unroll
    for (int h = 0; h < KS; h++) {
        const float* src = g_p[h] + (long)row * NC + col;
        v0 += src[0]; v1 += src[1];
    }
    if (col < 4096) {
        int pp = (col & 127) >> 1;
        float2 cs = g_tab[((row & 15) << 6) + pp];
        const float qs = 0.08838834764831845f * 1.4426950408889634f;
        float t = (v0 * cs.x - v1 * cs.y) * qs;
        v1 = (v0 * cs.y + v1 * cs.x) * qs; v0 = t;
        *(float2*)(g_q + (long)row * 4096 + col) = make_float2(v0, v1);
    } else if (col < 5120) {
        int c2 = col - 4096;
        int pp = (c2 & 127) >> 1;
        float2 cs = g_tab[((row & 15) << 6) + pp];
        float t = v0 * cs.x - v1 * cs.y;
        v1 = v0 * cs.y + v1 * cs.x; v0 = t;
        *(float2*)(g_kn + (long)row * 1024 + c2) = make_float2(v0, v1);
    } else {
        *(float2*)(g_vn + (long)row * 1024 + (col - 5120)) = make_float2(v0, v1);
    }
}

__global__ void out_combine_kernel(float* __restrict__ out) {
    int idx = blockIdx.x * 256 + threadIdx.x;
    float4 a = *(const float4*)(g_p[0] + 4 * (long)idx);
    float4 b = *(const float4*)(g_p[1] + 4 * (long)idx);
    float4 c = *(const float4*)(g_p[2] + 4 * (long)idx);
    float4 d = *(const float4*)(g_p[3] + 4 * (long)idx);
    *(float4*)(out + 4 * (long)idx) =
        make_float4(a.x + b.x + c.x + d.x, a.y + b.y + c.y + d.y,
                    a.z + b.z + c.z + d.z, a.w + b.w + c.w + d.w);
}

// ======================= attention: decoupled groups + ldmatrix fragments =======================
#define TC   64
#define SSTR 132
#define KW   68     // words/row, ≡4 mod 32 -> ldmatrix conflict-free
#define VW   36
#define QW   68
#define AOFF_K0  0
#define AOFF_K1  (TC*SSTR)
#define AOFF_V0  (2*TC*SSTR)
#define AOFF_V1  (3*TC*SSTR)
#define AOFF_KH  (4*TC*SSTR)
#define AOFF_VH  (AOFF_KH + TC*KW)
#define AOFF_QH  (AOFF_VH + 128*VW)
#define AOFF_EX  (AOFF_QH + 64*QW)
#define ATTN_SMEM_BYTES ((AOFF_EX + 512) * 4)
#define OBS  (TC*SSTR)

__device__ __forceinline__ void attn_load_kv2(
    const float* __restrict__ cache_k, const float* __restrict__ cache_v,
    int b, int kvh, int start, int kvlen, int t0, float* Ks, float* Vs,
    int wn, int gtid)
{
    int r = wn * 16 + (gtid >> 3);
    int c0 = (gtid & 7) * 4;
    int t = t0 + r;
    const float *sk, *sv;
    if (t < start) {
        long o = ((((long)b * MAXS_ + t) * KVH_) + kvh) * HD_;
        sk = cache_k + o; sv = cache_v + o;
    } else {
        int tt = min(t, kvlen - 1);
        long o = (((long)(b * S_ + (tt - start))) * KVH_ + kvh) * HD_;
        sk = g_kn + o; sv = g_vn + o;
    }
#pragma unroll
    for (int i = 0; i < 4; i++) {
        cpa16(Ks + r * SSTR + (c0 + i) * 4, sk + (c0 + i) * 4);
        cpa16(Vs + r * SSTR + (c0 + i) * 4, sv + (c0 + i) * 4);
    }
    cp_commit();
}

__global__ void __launch_bounds__(512, 1)
attn_kernel(const float* __restrict__ cache_k,
            const float* __restrict__ cache_v,
            const int* __restrict__ sp)
{
    extern __shared__ float sm[];
    float* KsB[2] = { sm + AOFF_K0, sm + AOFF_K1 };
    float* VsB[2] = { sm + AOFF_V0, sm + AOFF_V1 };
    unsigned* Kh = (unsigned*)(sm + AOFF_KH);
    unsigned* Vh = (unsigned*)(sm + AOFF_VH);
    unsigned* Qh = (unsigned*)(sm + AOFF_QH);
    float* ex = sm + AOFF_EX;

    int tid = threadIdx.x, lane = tid & 31, wid = tid >> 5;
    int b = blockIdx.x >> 3, kvh = blockIdx.x & 7;
    int start = sp[0], kvlen = start + S_;
    int wm = wid & 3, wn = wid >> 2;
    int gr = lane >> 2, kq = lane & 3;
    int rm = wm * 16;
    int gtid = wm * 32 + lane;

    // ---- ldmatrix lane addresses (bytes, shared space) ----
    unsigned sbase = (unsigned)__cvta_generic_to_shared(sm);
    unsigned qa_addr = sbase + AOFF_QH * 4 +
        (unsigned)(rm + (lane & 15)) * (QW * 4) + ((lane >> 4) << 4);
    unsigned kb_addr = sbase + AOFF_KH * 4 +
        (unsigned)(wn * 16 + (lane & 7) + ((lane >> 4) << 3)) * (KW * 4) +
        (((lane >> 3) & 1) << 4);
    unsigned vb_addr = sbase + AOFF_VH * 4 +
        (unsigned)((lane & 7) + ((lane >> 4) << 3)) * (VW * 4) +
        (unsigned)(wn * 32) + (((lane >> 3) & 1) << 4);

    // ---- Qh fill (fp16, once; g_q pre-scaled by 1/sqrt(HD)*log2e) ----
    {
        int r = tid >> 3, slot = tid & 7;
        const float* qp = g_q + (long)(b * S_ + (r & 15)) * D_ + (kvh * NREP_ + (r >> 4)) * HD_;
#pragma unroll
        for (int i = 0; i < 8; i++) {
            int w = slot + 8 * i;
            float2 v = *(const float2*)(qp + 2 * w);
            Qh[r * QW + w] = packh2(v.x, v.y);
        }
    }

    float m0r = -1e30f, m1r = -1e30f, l0r = 0.f, l1r = 0.f;
    float cacc[16][4];
#pragma unroll
    for (int nt = 0; nt < 16; nt++)
#pragma unroll
        for (int i = 0; i < 4; i++) cacc[nt][i] = 0.f;

    int NCH = (kvlen + TC - 1) / TC;
    attn_load_kv2(cache_k, cache_v, b, kvh, start, kvlen, 0,  KsB[0], VsB[0], wn, gtid);
    attn_load_kv2(cache_k, cache_v, b, kvh, start, kvlen, TC, KsB[1], VsB[1], wn, gtid);
    cp_wait<1>();
    __syncthreads();

    for (int j = 0; j < NCH; j++) {
        const float* Ks = KsB[j & 1];
        const float* Vs = VsB[j & 1];

        // ---- convert own tokens: K [tok][d-pair], V transposed [d][t-pair] ----
        {
            int tok = wn * 16 + (gtid >> 3), slot = gtid & 7;
            const float* kr = Ks + tok * SSTR;
            unsigned* kd = Kh + tok * KW;
#pragma unroll
            for (int i = 0; i < 8; i++) {
                int w = slot + 8 * i;
                float2 v = *(const float2*)(kr + 2 * w);
                kd[w] = packh2(v.x, v.y);
            }
            int d = gtid;
#pragma unroll
            for (int i = 0; i < 8; i++) {
                int pl = wn * 8 + i;
                Vh[d * VW + pl] = packh2(Vs[(2 * pl) * SSTR + d],
                                         Vs[(2 * pl + 1) * SSTR + d]);
            }
        }
        GROUP_BAR(1 + wn);

        if (j + 2 < NCH)
            attn_load_kv2(cache_k, cache_v, b, kvh, start, kvlen,
                          (j + 2) * TC, KsB[j & 1], VsB[j & 1], wn, gtid);

        // ---- S = Q K^T over own 16 tokens (ldmatrix fragments) ----
        float sacc[2][4];
#pragma unroll
        for (int nt = 0; nt < 2; nt++)
#pragma unroll
            for (int i = 0; i < 4; i++) sacc[nt][i] = 0.f;
#pragma unroll
        for (int kb = 0; kb < 8; kb++) {
            unsigned a0, a1, a2, a3, b0, b1, b2, b3;
            ldsm4(a0, a1, a2, a3, qa_addr + kb * 32);
            ldsm4(b0, b1, b2, b3, kb_addr + kb * 32);
            mma16h(sacc[0], a0, a1, a2, a3, b0, b1);
            mma16h(sacc[1], a0, a1, a2, a3, b2, b3);
        }

        if (j == NCH - 1 && (kvlen & (TC - 1))) {   // never for kvlen=4096
#pragma unroll
            for (int nt = 0; nt < 2; nt++) {
                int tk = j * TC + wn * 16 + nt * 8 + 2 * kq;
                if (tk >= kvlen)     { sacc[nt][0] = -1e30f; sacc[nt][2] = -1e30f; }
                if (tk + 1 >= kvlen) { sacc[nt][1] = -1e30f; sacc[nt][3] = -1e30f; }
            }
        }

        // ---- warp-local online softmax ----
        float mw0 = fmaxf(fmaxf(sacc[0][0], sacc[0][1]), fmaxf(sacc[1][0], sacc[1][1]));
        float mw1 = fmaxf(fmaxf(sacc[0][2], sacc[0][3]), fmaxf(sacc[1][2], sacc[1][3]));
        mw0 = fmaxf(mw0, __shfl_xor_sync(0xffffffffu, mw0, 1));
        mw0 = fmaxf(mw0, __shfl_xor_sync(0xffffffffu, mw0, 2));
        mw1 = fmaxf(mw1, __shfl_xor_sync(0xffffffffu, mw1, 1));
        mw1 = fmaxf(mw1, __shfl_xor_sync(0xffffffffu, mw1, 2));
        float M0 = fmaxf(m0r, mw0), M1 = fmaxf(m1r, mw1);
        if (__any_sync(0xffffffffu, (M0 > m0r) | (M1 > m1r))) {
            float sc0 = ex2f(m0r - M0), sc1 = ex2f(m1r - M1);
            l0r *= sc0;  l1r *= sc1;
#pragma unroll
            for (int nt = 0; nt < 16; nt++) {
                cacc[nt][0] *= sc0; cacc[nt][1] *= sc0;
                cacc[nt][2] *= sc1; cacc[nt][3] *= sc1;
            }
            m0r = M0;  m1r = M1;
        }
        float Mb0 = M0 - 8.f, Mb1 = M1 - 8.f;
        float g00 = ex2f(sacc[0][0] - Mb0), g01 = ex2f(sacc[0][1] - Mb0);
        float g02 = ex2f(sacc[0][2] - Mb1), g03 = ex2f(sacc[0][3] - Mb1);
        float h00 = ex2f(sacc[1][0] - Mb0), h01 = ex2f(sacc[1][1] - Mb0);
        float h02 = ex2f(sacc[1][2] - Mb1), h03 = ex2f(sacc[1][3] - Mb1);
        l0r += (g00 + g01) + (h00 + h01);
        l1r += (g02 + g03) + (h02 + h03);
        unsigned pa0 = packh2(g00, g01), pa1 = packh2(g02, g03);
        unsigned pa2 = packh2(h00, h01), pa3 = packh2(h02, h03);

        // ---- O += P V over own 16 tokens x 128 dims (ldmatrix B, register A) ----
#pragma unroll
        for (int ntp = 0; ntp < 8; ntp++) {
            unsigned b00, b01, b10, b11;
            ldsm4(b00, b01, b10, b11, vb_addr + (unsigned)(ntp * 16 * VW * 4));
            mma16h(cacc[2 * ntp],     pa0, pa1, pa2, pa3, b00, b01);
            mma16h(cacc[2 * ntp + 1], pa0, pa1, pa2, pa3, b10, b11);
        }

        if (j + 1 < NCH) { if (j + 2 < NCH) { cp_wait<1>(); } else { cp_wait<0>(); } }
        GROUP_BAR(1 + wn);
    }

    // ---- epilogue: exact merge of the 4 group-partials ----
    l0r += __shfl_xor_sync(0xffffffffu, l0r, 1);
    l0r += __shfl_xor_sync(0xffffffffu, l0r, 2);
    l1r += __shfl_xor_sync(0xffffffffu, l1r, 1);
    l1r += __shfl_xor_sync(0xffffffffu, l1r, 2);
    if (kq == 0) { ex[wn * 64 + rm + gr] = m0r; ex[wn * 64 + rm + gr + 8] = m1r; }
    __syncthreads();
    float M0 = -1e30f, M1 = -1e30f;
#pragma unroll
    for (int w = 0; w < 4; w++) {
        M0 = fmaxf(M0, ex[w * 64 + rm + gr]);
        M1 = fmaxf(M1, ex[w * 64 + rm + gr + 8]);
    }
    float sc0 = ex2f(m0r - M0), sc1 = ex2f(m1r - M1);
    if (kq == 0) {
        ex[256 + wn * 64 + rm + gr]     = l0r * sc0;
        ex[256 + wn * 64 + rm + gr + 8] = l1r * sc1;
    }
    float* Ob = sm + wn * OBS;
#pragma unroll
    for (int nt = 0; nt < 16; nt++) {
        int d = nt * 8 + 2 * kq;
        *(float2*)&Ob[(rm + gr) * SSTR + d] =
            make_float2(cacc[nt][0] * sc0, cacc[nt][1] * sc0);
        *(float2*)&Ob[(rm + gr + 8) * SSTR + d] =
            make_float2(cacc[nt][2] * sc1, cacc[nt][3] * sc1);
    }
    __syncthreads();
#pragma unroll
    for (int i = 0; i < 4; i++) {
        int f = i * 512 + tid;
        int r = f >> 5, d4 = f & 31;
        float4 s0 = *(const float4*)&sm[0 * OBS + r * SSTR + d4 * 4];
        float4 s1 = *(const float4*)&sm[1 * OBS + r * SSTR + d4 * 4];
        float4 s2 = *(const float4*)&sm[2 * OBS + r * SSTR + d4 * 4];
        float4 s3 = *(const float4*)&sm[3 * OBS + r * SSTR + d4 * 4];
        float L = ex[256 + r] + ex[256 + 64 + r] + ex[256 + 128 + r] + ex[256 + 192 + r];
        float inv = 1.f / L;
        float4 o = make_float4((s0.x + s1.x + s2.x + s3.x) * inv,
                               (s0.y + s1.y + s2.y + s3.y) * inv,
                               (s0.z + s1.z + s2.z + s3.z) * inv,
                               (s0.w + s1.w + s2.w + s3.w) * inv);
        *(float4*)(g_ctx + (long)(b * S_ + (r & 15)) * D_ +
                   (kvh * NREP_ + (r >> 4)) * HD_ + d4 * 4) = o;
    }
}

// ======================= launch =======================
extern "C" void kernel_launch(void* const* d_in, const int* in_sizes, int n_in,
                              void* d_out, int out_size) {
    const float* x       = (const float*)d_in[0];
    const float* Wq      = (const float*)d_in[1];
    const float* Wk      = (const float*)d_in[2];
    const float* Wv      = (const float*)d_in[3];
    const float* Wo      = (const float*)d_in[4];
    const float* cache_k = (const float*)d_in[5];
    const float* cache_v = (const float*)d_in[6];
    const int*   sp      = (const int*)d_in[7];
    float* out = (float*)d_out;

    cudaFuncSetAttribute(qkv_kernel,  cudaFuncAttributeMaxDynamicSharedMemorySize, GEMM_SMEM_BYTES);
    cudaFuncSetAttribute(out_kernel,  cudaFuncAttributeMaxDynamicSharedMemorySize, GEMM_SMEM_BYTES);
    cudaFuncSetAttribute(attn_kernel, cudaFuncAttributeMaxDynamicSharedMemorySize, ATTN_SMEM_BYTES);

    rope_tab_kernel<<<1, 1024>>>(sp);
    qkv_kernel<<<dim3(2, 48, KS), 256, GEMM_SMEM_BYTES>>>(x, Wq, Wk, Wv);
    qkv_combine_kernel<<<(MROWS * NC / 2) / 256, 256>>>();
    attn_kernel<<<128, 512, ATTN_SMEM_BYTES>>>(cache_k, cache_v, sp);
    out_kernel<<<dim3(2, 32, KS), 256, GEMM_SMEM_BYTES>>>(Wo);
    out_combine_kernel<<<(MROWS * D_ / 4) / 256, 256>>>(out);
}

// round 14
// speedup vs baseline: 1.2093x; 1.1392x over previous
#include <cuda_runtime.h>
#include <cuda_bf16.h>
#include <cstdint>

#define B_    16
#define S_    16
#define D_    4096
#define H_    32
#define KVH_  8
#define HD_   128
#define NREP_ 4
#define MAXS_ 4096
#define MROWS 256
#define KS    4
#define NC    6144

__device__ float  g_q  [MROWS * D_];
__device__ float  g_kn [MROWS * KVH_ * HD_];
__device__ float  g_vn [MROWS * KVH_ * HD_];
__device__ float  g_ctx[MROWS * D_];
__device__ float  g_p  [KS][MROWS * NC];
__device__ float2 g_tab[S_ * 64];

__device__ __forceinline__ unsigned f2tf(float x) {
    unsigned r; asm("cvt.rna.tf32.f32 %0, %1;" : "=r"(r) : "f"(x)); return r;
}
__device__ __forceinline__ void mma8(float* d, unsigned a0, unsigned a1, unsigned a2,
                                     unsigned a3, unsigned b0, unsigned b1) {
    asm volatile(
        "mma.sync.aligned.m16n8k8.row.col.f32.tf32.tf32.f32 "
        "{%0,%1,%2,%3}, {%4,%5,%6,%7}, {%8,%9}, {%0,%1,%2,%3};"
        : "+f"(d[0]), "+f"(d[1]), "+f"(d[2]), "+f"(d[3])
        : "r"(a0), "r"(a1), "r"(a2), "r"(a3), "r"(b0), "r"(b1));
}
__device__ __forceinline__ void mma16h(float* d, unsigned a0, unsigned a1, unsigned a2,
                                       unsigned a3, unsigned b0, unsigned b1) {
    asm volatile(
        "mma.sync.aligned.m16n8k16.row.col.f32.f16.f16.f32 "
        "{%0,%1,%2,%3}, {%4,%5,%6,%7}, {%8,%9}, {%0,%1,%2,%3};"
        : "+f"(d[0]), "+f"(d[1]), "+f"(d[2]), "+f"(d[3])
        : "r"(a0), "r"(a1), "r"(a2), "r"(a3), "r"(b0), "r"(b1));
}
__device__ __forceinline__ void ldsm4(unsigned& r0, unsigned& r1, unsigned& r2,
                                      unsigned& r3, unsigned addr) {
    asm volatile("ldmatrix.sync.aligned.m8n8.x4.shared.b16 {%0,%1,%2,%3}, [%4];"
                 : "=r"(r0), "=r"(r1), "=r"(r2), "=r"(r3) : "r"(addr));
}
__device__ __forceinline__ void ldsm4t(unsigned& r0, unsigned& r1, unsigned& r2,
                                       unsigned& r3, unsigned addr) {
    asm volatile("ldmatrix.sync.aligned.m8n8.x4.trans.shared.b16 {%0,%1,%2,%3}, [%4];"
                 : "=r"(r0), "=r"(r1), "=r"(r2), "=r"(r3) : "r"(addr));
}
__device__ __forceinline__ float ex2f(float x) {
    float r; asm("ex2.approx.f32 %0, %1;" : "=f"(r) : "f"(x)); return r;
}
__device__ __forceinline__ unsigned packh2(float lo, float hi) {
    unsigned d; asm("cvt.rn.f16x2.f32 %0, %1, %2;" : "=r"(d) : "f"(hi), "f"(lo)); return d;
}
__device__ __forceinline__ void cpa16(float* s, const float* g) {
    unsigned sa = (unsigned)__cvta_generic_to_shared(s);
    asm volatile("cp.async.cg.shared.global [%0], [%1], 16;" :: "r"(sa), "l"(g));
}
__device__ __forceinline__ void cp_commit() { asm volatile("cp.async.commit_group;"); }
template<int N> __device__ __forceinline__ void cp_wait() {
    asm volatile("cp.async.wait_group %0;" :: "n"(N));
}
#define GROUP_BAR(id) asm volatile("bar.sync %0, 128;" :: "r"(id) : "memory")

// ======================= rope table =======================
__global__ void rope_tab_kernel(const int* __restrict__ sp) {
    int idx = threadIdx.x;
    int s = idx >> 6, pp = idx & 63;
    double f = (double)(sp[0] + s) * exp(-9.210340371976184 * ((double)pp / 64.0));
    double cd, sd; sincos(f, &sd, &cd);
    g_tab[idx] = make_float2((float)cd, (float)sd);
}

// ======================= GEMM 128x128, K-split =======================
#define BM 128
#define BK 32
#define AST 36
#define BST 136
#define GEMM_SMEM_BYTES ((2*BM*AST + 2*BK*BST) * 4)

__device__ void gemm_tile(const float* __restrict__ A, int lda,
                          const float* __restrict__ W, int ldw,
                          float* __restrict__ C, int ldc,
                          int m0, int n0w, int n0c, int kbase, int KT)
{
    extern __shared__ float sm[];
    float* As0 = sm;
    float* As1 = sm + BM * AST;
    float* Bs0 = sm + 2 * BM * AST;
    float* Bs1 = sm + 2 * BM * AST + BK * BST;

    int tid = threadIdx.x, lane = tid & 31, wid = tid >> 5;
    int wm = wid >> 2, wn = wid & 3;
    int gr = lane >> 2, kq = lane & 3;

    float acc[4][4][4];
#pragma unroll
    for (int mt = 0; mt < 4; mt++)
#pragma unroll
        for (int nt = 0; nt < 4; nt++)
#pragma unroll
            for (int i = 0; i < 4; i++) acc[mt][nt][i] = 0.f;

    {
#pragma unroll
        for (int i = 0; i < 4; i++) {
            int idx = i * 256 + tid; int r = idx >> 3, c4 = idx & 7;
            cpa16(As0 + r * AST + c4 * 4, A + (long)(m0 + r) * lda + kbase + c4 * 4);
        }
#pragma unroll
        for (int i = 0; i < 4; i++) {
            int idx = i * 256 + tid; int r = idx >> 5, c4 = idx & 31;
            cpa16(Bs0 + r * BST + c4 * 4, W + (long)(kbase + r) * ldw + n0w + c4 * 4);
        }
        cp_commit();
    }

    for (int kt = 0; kt < KT; kt++) {
        float* Ab = (kt & 1) ? As1 : As0;
        float* Bb = (kt & 1) ? Bs1 : Bs0;
        if (kt + 1 < KT) {
            float* An = (kt & 1) ? As0 : As1;
            float* Bn = (kt & 1) ? Bs0 : Bs1;
            int k1 = kbase + (kt + 1) * BK;
#pragma unroll
            for (int i = 0; i < 4; i++) {
                int idx = i * 256 + tid; int r = idx >> 3, c4 = idx & 7;
                cpa16(An + r * AST + c4 * 4, A + (long)(m0 + r) * lda + k1 + c4 * 4);
            }
#pragma unroll
            for (int i = 0; i < 4; i++) {
                int idx = i * 256 + tid; int r = idx >> 5, c4 = idx & 31;
                cpa16(Bn + r * BST + c4 * 4, W + (long)(k1 + r) * ldw + n0w + c4 * 4);
            }
            cp_commit();
            cp_wait<1>();
        } else {
            cp_wait<0>();
        }
        __syncthreads();
#pragma unroll
        for (int kk = 0; kk < 4; kk++) {
            unsigned af[4][4], bf[4][2];
#pragma unroll
            for (int mt = 0; mt < 4; mt++) {
                int rm = wm * 64 + mt * 16;
                const float* p0 = Ab + (rm + gr) * AST + kk * 8 + kq;
                const float* p1 = Ab + (rm + gr + 8) * AST + kk * 8 + kq;
                af[mt][0] = f2tf(p0[0]); af[mt][1] = f2tf(p1[0]);
                af[mt][2] = f2tf(p0[4]); af[mt][3] = f2tf(p1[4]);
            }
#pragma unroll
            for (int nt = 0; nt < 4; nt++) {
                int cb = wn * 32 + nt * 8 + gr;
                bf[nt][0] = f2tf(Bb[(kk * 8 + kq) * BST + cb]);
                bf[nt][1] = f2tf(Bb[(kk * 8 + kq + 4) * BST + cb]);
            }
#pragma unroll
            for (int mt = 0; mt < 4; mt++)
#pragma unroll
                for (int nt = 0; nt < 4; nt++)
                    mma8(acc[mt][nt], af[mt][0], af[mt][1], af[mt][2], af[mt][3],
                         bf[nt][0], bf[nt][1]);
        }
        __syncthreads();
    }

#pragma unroll
    for (int mt = 0; mt < 4; mt++)
#pragma unroll
        for (int nt = 0; nt < 4; nt++) {
            int row = m0 + wm * 64 + mt * 16 + gr;
            int col = n0c + wn * 32 + nt * 8 + 2 * kq;
            *(float2*)(C + (long)row * ldc + col) =
                make_float2(acc[mt][nt][0], acc[mt][nt][1]);
            *(float2*)(C + (long)(row + 8) * ldc + col) =
                make_float2(acc[mt][nt][2], acc[mt][nt][3]);
        }
}

__global__ void qkv_kernel(const float* __restrict__ x, const float* __restrict__ Wq,
                           const float* __restrict__ Wk, const float* __restrict__ Wv) {
    int y = blockIdx.y, z = blockIdx.z;
    const float* W; int ldw, n0w, n0c;
    if (y < 32)      { W = Wq; ldw = 4096; n0w = y * 128;        n0c = y * 128; }
    else if (y < 40) { W = Wk; ldw = 1024; n0w = (y - 32) * 128; n0c = 4096 + (y - 32) * 128; }
    else             { W = Wv; ldw = 1024; n0w = (y - 40) * 128; n0c = 5120 + (y - 40) * 128; }
    gemm_tile(x, 4096, W, ldw, g_p[z], NC, blockIdx.x * BM, n0w, n0c, z * 1024, 32);
}

__global__ void out_kernel(const float* __restrict__ Wo) {
    int z = blockIdx.z;
    gemm_tile(g_ctx, 4096, Wo, 4096, g_p[z], 4096,
              blockIdx.x * BM, blockIdx.y * 128, blockIdx.y * 128, z * 1024, 32);
}

// ======================= combines =======================
__global__ void qkv_combine_kernel() {
    int idx = blockIdx.x * 256 + threadIdx.x;
    int row = idx / (NC / 2);
    int p   = idx - row * (NC / 2);
    int col = 2 * p;
    float v0 = 0.f, v1 = 0.f;
#pragma unroll
    for (int h = 0; h < KS; h++) {
        const float* src = g_p[h] + (long)row * NC + col;
        v0 += src[0]; v1 += src[1];
    }
    if (col < 4096) {
        int pp = (col & 127) >> 1;
        float2 cs = g_tab[((row & 15) << 6) + pp];
        const float qs = 0.08838834764831845f * 1.4426950408889634f;
        float t = (v0 * cs.x - v1 * cs.y) * qs;
        v1 = (v0 * cs.y + v1 * cs.x) * qs; v0 = t;
        *(float2*)(g_q + (long)row * 4096 + col) = make_float2(v0, v1);
    } else if (col < 5120) {
        int c2 = col - 4096;
        int pp = (c2 & 127) >> 1;
        float2 cs = g_tab[((row & 15) << 6) + pp];
        float t = v0 * cs.x - v1 * cs.y;
        v1 = v0 * cs.y + v1 * cs.x; v0 = t;
        *(float2*)(g_kn + (long)row * 1024 + c2) = make_float2(v0, v1);
    } else {
        *(float2*)(g_vn + (long)row * 1024 + (col - 5120)) = make_float2(v0, v1);
    }
}

__global__ void out_combine_kernel(float* __restrict__ out) {
    int idx = blockIdx.x * 256 + threadIdx.x;
    float4 a = *(const float4*)(g_p[0] + 4 * (long)idx);
    float4 b = *(const float4*)(g_p[1] + 4 * (long)idx);
    float4 c = *(const float4*)(g_p[2] + 4 * (long)idx);
    float4 d = *(const float4*)(g_p[3] + 4 * (long)idx);
    *(float4*)(out + 4 * (long)idx) =
        make_float4(a.x + b.x + c.x + d.x, a.y + b.y + c.y + d.y,
                    a.z + b.z + c.z + d.z, a.w + b.w + c.w + d.w);
}

// ======================= attention: direct-LDG fp16, ldmatrix(.trans) =======================
#define TC   64
#define SSTR 132    // epilogue O-partial stride
#define KW   68     // Kh row words (64 d-pairs + pad), ≡4 mod 32
#define VW   68     // Vh row words, same
#define QW   68
#define AOFF_KH  0
#define AOFF_VH  (TC*KW)
#define AOFF_QH  (AOFF_VH + TC*VW)
#define OBS      (TC*SSTR)
#define AOFF_EX  (4*OBS)
#define ATTN_SMEM_BYTES ((AOFF_EX + 512) * 4)

__global__ void __launch_bounds__(512, 1)
attn_kernel(const float* __restrict__ cache_k,
            const float* __restrict__ cache_v,
            const int* __restrict__ sp)
{
    extern __shared__ float sm[];
    unsigned* Kh = (unsigned*)(sm + AOFF_KH);
    unsigned* Vh = (unsigned*)(sm + AOFF_VH);
    unsigned* Qh = (unsigned*)(sm + AOFF_QH);
    float* ex = sm + AOFF_EX;

    int tid = threadIdx.x, lane = tid & 31, wid = tid >> 5;
    int b = blockIdx.x >> 3, kvh = blockIdx.x & 7;
    int start = sp[0], kvlen = start + S_;
    int wm = wid & 3, wn = wid >> 2;
    int gr = lane >> 2, kq = lane & 3;
    int rm = wm * 16;
    int gtid = wm * 32 + lane;

    // per-thread load slot: own token, 16-float slice
    int tok  = wn * 16 + (gtid >> 3);
    int slot = gtid & 7;

    // ldmatrix lane addresses (bytes)
    unsigned sbase = (unsigned)__cvta_generic_to_shared(sm);
    unsigned qa_addr = sbase + AOFF_QH * 4 +
        (unsigned)(rm + (lane & 15)) * (QW * 4) + ((lane >> 4) << 4);
    unsigned kb_addr = sbase + AOFF_KH * 4 +
        (unsigned)(wn * 16 + (lane & 7) + ((lane >> 4) << 3)) * (KW * 4) +
        (((lane >> 3) & 1) << 4);
    unsigned vb_addr = sbase + AOFF_VH * 4 +
        (unsigned)(wn * 16 + (lane & 7) + (((lane >> 3) & 1) << 3)) * (VW * 4) +
        ((lane >> 4) << 4);

    // ---- Qh fill (fp16, once; g_q pre-scaled by 1/sqrt(HD)*log2e) ----
    {
        int r = tid >> 3, sl = tid & 7;
        const float* qp = g_q + (long)(b * S_ + (r & 15)) * D_ + (kvh * NREP_ + (r >> 4)) * HD_;
#pragma unroll
        for (int i = 0; i < 8; i++) {
            int w = sl + 8 * i;
            float2 v = *(const float2*)(qp + 2 * w);
            Qh[r * QW + w] = packh2(v.x, v.y);
        }
    }

    float m0r = -1e30f, m1r = -1e30f, l0r = 0.f, l1r = 0.f;
    float cacc[16][4];
#pragma unroll
    for (int nt = 0; nt < 16; nt++)
#pragma unroll
        for (int i = 0; i < 4; i++) cacc[nt][i] = 0.f;

    unsigned kh[8], vh[8];
    auto prefetch = [&](int t0) {
        int t = t0 + tok;
        const float *sk, *sv;
        if (t < start) {
            long o = ((((long)b * MAXS_ + t) * KVH_) + kvh) * HD_;
            sk = cache_k + o; sv = cache_v + o;
        } else {
            int tt = min(t, kvlen - 1);
            long o = (((long)(b * S_ + (tt - start))) * KVH_ + kvh) * HD_;
            sk = g_kn + o; sv = g_vn + o;
        }
        const float4* k4 = (const float4*)(sk + slot * 16);
        const float4* v4 = (const float4*)(sv + slot * 16);
#pragma unroll
        for (int i = 0; i < 4; i++) {
            float4 kv = k4[i];
            float4 vv = v4[i];
            kh[2 * i]     = packh2(kv.x, kv.y);
            kh[2 * i + 1] = packh2(kv.z, kv.w);
            vh[2 * i]     = packh2(vv.x, vv.y);
            vh[2 * i + 1] = packh2(vv.z, vv.w);
        }
    };

    int NCH = (kvlen + TC - 1) / TC;
    prefetch(0);
    __syncthreads();    // Qh visible

    for (int j = 0; j < NCH; j++) {
        // ---- store prefetched chunk j to fp16 smem ----
        *(uint4*)&Kh[tok * KW + slot * 8]     = make_uint4(kh[0], kh[1], kh[2], kh[3]);
        *(uint4*)&Kh[tok * KW + slot * 8 + 4] = make_uint4(kh[4], kh[5], kh[6], kh[7]);
        *(uint4*)&Vh[tok * VW + slot * 8]     = make_uint4(vh[0], vh[1], vh[2], vh[3]);
        *(uint4*)&Vh[tok * VW + slot * 8 + 4] = make_uint4(vh[4], vh[5], vh[6], vh[7]);
        GROUP_BAR(1 + wn);

        if (j + 1 < NCH) prefetch((j + 1) * TC);

        // ---- S = Q K^T over own 16 tokens (ldmatrix) ----
        float sacc[2][4];
#pragma unroll
        for (int nt = 0; nt < 2; nt++)
#pragma unroll
            for (int i = 0; i < 4; i++) sacc[nt][i] = 0.f;
#pragma unroll
        for (int kb = 0; kb < 8; kb++) {
            unsigned a0, a1, a2, a3, b0, b1, b2, b3;
            ldsm4(a0, a1, a2, a3, qa_addr + kb * 32);
            ldsm4(b0, b1, b2, b3, kb_addr + kb * 32);
            mma16h(sacc[0], a0, a1, a2, a3, b0, b1);
            mma16h(sacc[1], a0, a1, a2, a3, b2, b3);
        }

        if (j == NCH - 1 && (kvlen & (TC - 1))) {   // never for kvlen=4096
#pragma unroll
            for (int nt = 0; nt < 2; nt++) {
                int tk = j * TC + wn * 16 + nt * 8 + 2 * kq;
                if (tk >= kvlen)     { sacc[nt][0] = -1e30f; sacc[nt][2] = -1e30f; }
                if (tk + 1 >= kvlen) { sacc[nt][1] = -1e30f; sacc[nt][3] = -1e30f; }
            }
        }

        // ---- warp-local online softmax ----
        float mw0 = fmaxf(fmaxf(sacc[0][0], sacc[0][1]), fmaxf(sacc[1][0], sacc[1][1]));
        float mw1 = fmaxf(fmaxf(sacc[0][2], sacc[0][3]), fmaxf(sacc[1][2], sacc[1][3]));
        mw0 = fmaxf(mw0, __shfl_xor_sync(0xffffffffu, mw0, 1));
        mw0 = fmaxf(mw0, __shfl_xor_sync(0xffffffffu, mw0, 2));
        mw1 = fmaxf(mw1, __shfl_xor_sync(0xffffffffu, mw1, 1));
        mw1 = fmaxf(mw1, __shfl_xor_sync(0xffffffffu, mw1, 2));
        float M0 = fmaxf(m0r, mw0), M1 = fmaxf(m1r, mw1);
        if (__any_sync(0xffffffffu, (M0 > m0r) | (M1 > m1r))) {
            float sc0 = ex2f(m0r - M0), sc1 = ex2f(m1r - M1);
            l0r *= sc0;  l1r *= sc1;
#pragma unroll
            for (int nt = 0; nt < 16; nt++) {
                cacc[nt][0] *= sc0; cacc[nt][1] *= sc0;
                cacc[nt][2] *= sc1; cacc[nt][3] *= sc1;
            }
            m0r = M0;  m1r = M1;
        }
        float Mb0 = M0 - 8.f, Mb1 = M1 - 8.f;
        float g00 = ex2f(sacc[0][0] - Mb0), g01 = ex2f(sacc[0][1] - Mb0);
        float g02 = ex2f(sacc[0][2] - Mb1), g03 = ex2f(sacc[0][3] - Mb1);
        float h00 = ex2f(sacc[1][0] - Mb0), h01 = ex2f(sacc[1][1] - Mb0);
        float h02 = ex2f(sacc[1][2] - Mb1), h03 = ex2f(sacc[1][3] - Mb1);
        l0r += (g00 + g01) + (h00 + h01);
        l1r += (g02 + g03) + (h02 + h03);
        unsigned pa0 = packh2(g00, g01), pa1 = packh2(g02, g03);
        unsigned pa2 = packh2(h00, h01), pa3 = packh2(h02, h03);

        // ---- O += P V over own 16 tokens x 128 dims (ldmatrix.trans B) ----
#pragma unroll
        for (int db = 0; db < 8; db++) {
            unsigned b00, b01, b10, b11;
            ldsm4t(b00, b01, b10, b11, vb_addr + db * 32);
            mma16h(cacc[2 * db],     pa0, pa1, pa2, pa3, b00, b01);
            mma16h(cacc[2 * db + 1], pa0, pa1, pa2, pa3, b10, b11);
        }

        GROUP_BAR(1 + wn);   // all reads of Kh/Vh(j) done -> next STS safe
    }

    // ---- epilogue: exact merge of the 4 group-partials ----
    l0r += __shfl_xor_sync(0xffffffffu, l0r, 1);
    l0r += __shfl_xor_sync(0xffffffffu, l0r, 2);
    l1r += __shfl_xor_sync(0xffffffffu, l1r, 1);
    l1r += __shfl_xor_sync(0xffffffffu, l1r, 2);
    if (kq == 0) { ex[wn * 64 + rm + gr] = m0r; ex[wn * 64 + rm + gr + 8] = m1r; }
    __syncthreads();
    float M0 = -1e30f, M1 = -1e30f;
#pragma unroll
    for (int w = 0; w < 4; w++) {
        M0 = fmaxf(M0, ex[w * 64 + rm + gr]);
        M1 = fmaxf(M1, ex[w * 64 + rm + gr + 8]);
    }
    float sc0 = ex2f(m0r - M0), sc1 = ex2f(m1r - M1);
    if (kq == 0) {
        ex[256 + wn * 64 + rm + gr]     = l0r * sc0;
        ex[256 + wn * 64 + rm + gr + 8] = l1r * sc1;
    }
    float* Ob = sm + wn * OBS;
#pragma unroll
    for (int nt = 0; nt < 16; nt++) {
        int d = nt * 8 + 2 * kq;
        *(float2*)&Ob[(rm + gr) * SSTR + d] =
            make_float2(cacc[nt][0] * sc0, cacc[nt][1] * sc0);
        *(float2*)&Ob[(rm + gr + 8) * SSTR + d] =
            make_float2(cacc[nt][2] * sc1, cacc[nt][3] * sc1);
    }
    __syncthreads();
#pragma unroll
    for (int i = 0; i < 4; i++) {
        int f = i * 512 + tid;
        int r = f >> 5, d4 = f & 31;
        float4 s0 = *(const float4*)&sm[0 * OBS + r * SSTR + d4 * 4];
        float4 s1 = *(const float4*)&sm[1 * OBS + r * SSTR + d4 * 4];
        float4 s2 = *(const float4*)&sm[2 * OBS + r * SSTR + d4 * 4];
        float4 s3 = *(const float4*)&sm[3 * OBS + r * SSTR + d4 * 4];
        float L = ex[256 + r] + ex[256 + 64 + r] + ex[256 + 128 + r] + ex[256 + 192 + r];
        float inv = 1.f / L;
        float4 o = make_float4((s0.x + s1.x + s2.x + s3.x) * inv,
                               (s0.y + s1.y + s2.y + s3.y) * inv,
                               (s0.z + s1.z + s2.z + s3.z) * inv,
                               (s0.w + s1.w + s2.w + s3.w) * inv);
        *(float4*)(g_ctx + (long)(b * S_ + (r & 15)) * D_ +
                   (kvh * NREP_ + (r >> 4)) * HD_ + d4 * 4) = o;
    }
}

// ======================= launch =======================
extern "C" void kernel_launch(void* const* d_in, const int* in_sizes, int n_in,
                              void* d_out, int out_size) {
    const float* x       = (const float*)d_in[0];
    const float* Wq      = (const float*)d_in[1];
    const float* Wk      = (const float*)d_in[2];
    const float* Wv      = (const float*)d_in[3];
    const float* Wo      = (const float*)d_in[4];
    const float* cache_k = (const float*)d_in[5];
    const float* cache_v = (const float*)d_in[6];
    const int*   sp      = (const int*)d_in[7];
    float* out = (float*)d_out;

    cudaFuncSetAttribute(qkv_kernel,  cudaFuncAttributeMaxDynamicSharedMemorySize, GEMM_SMEM_BYTES);
    cudaFuncSetAttribute(out_kernel,  cudaFuncAttributeMaxDynamicSharedMemorySize, GEMM_SMEM_BYTES);
    cudaFuncSetAttribute(attn_kernel, cudaFuncAttributeMaxDynamicSharedMemorySize, ATTN_SMEM_BYTES);

    rope_tab_kernel<<<1, 1024>>>(sp);
    qkv_kernel<<<dim3(2, 48, KS), 256, GEMM_SMEM_BYTES>>>(x, Wq, Wk, Wv);
    qkv_combine_kernel<<<(MROWS * NC / 2) / 256, 256>>>();
    attn_kernel<<<128, 512, ATTN_SMEM_BYTES>>>(cache_k, cache_v, sp);
    out_kernel<<<dim3(2, 32, KS), 256, GEMM_SMEM_BYTES>>>(Wo);
    out_combine_kernel<<<(MROWS * D_ / 4) / 256, 256>>>(out);
}

// round 15
// speedup vs baseline: 1.2253x; 1.0132x over previous
#include <cuda_runtime.h>
#include <cuda_bf16.h>
#include <cstdint>

#define B_    16
#define S_    16
#define D_    4096
#define H_    32
#define KVH_  8
#define HD_   128
#define NREP_ 4
#define MAXS_ 4096
#define MROWS 256
#define KS    4
#define NC    6144

__device__ float  g_q  [MROWS * D_];
__device__ float  g_kn [MROWS * KVH_ * HD_];
__device__ float  g_vn [MROWS * KVH_ * HD_];
__device__ float  g_ctx[MROWS * D_];
__device__ float  g_p  [KS][MROWS * NC];
__device__ float2 g_tab[S_ * 64];

__device__ __forceinline__ void mma16h(float* d, unsigned a0, unsigned a1, unsigned a2,
                                       unsigned a3, unsigned b0, unsigned b1) {
    asm volatile(
        "mma.sync.aligned.m16n8k16.row.col.f32.f16.f16.f32 "
        "{%0,%1,%2,%3}, {%4,%5,%6,%7}, {%8,%9}, {%0,%1,%2,%3};"
        : "+f"(d[0]), "+f"(d[1]), "+f"(d[2]), "+f"(d[3])
        : "r"(a0), "r"(a1), "r"(a2), "r"(a3), "r"(b0), "r"(b1));
}
__device__ __forceinline__ void ldsm4(unsigned& r0, unsigned& r1, unsigned& r2,
                                      unsigned& r3, unsigned addr) {
    asm volatile("ldmatrix.sync.aligned.m8n8.x4.shared.b16 {%0,%1,%2,%3}, [%4];"
                 : "=r"(r0), "=r"(r1), "=r"(r2), "=r"(r3) : "r"(addr));
}
__device__ __forceinline__ void ldsm4t(unsigned& r0, unsigned& r1, unsigned& r2,
                                       unsigned& r3, unsigned addr) {
    asm volatile("ldmatrix.sync.aligned.m8n8.x4.trans.shared.b16 {%0,%1,%2,%3}, [%4];"
                 : "=r"(r0), "=r"(r1), "=r"(r2), "=r"(r3) : "r"(addr));
}
__device__ __forceinline__ float ex2f(float x) {
    float r; asm("ex2.approx.f32 %0, %1;" : "=f"(r) : "f"(x)); return r;
}
__device__ __forceinline__ unsigned packh2(float lo, float hi) {
    unsigned d; asm("cvt.rn.f16x2.f32 %0, %1, %2;" : "=r"(d) : "f"(hi), "f"(lo)); return d;
}
#define GROUP_BAR(id) asm volatile("bar.sync %0, 128;" :: "r"(id) : "memory")

// ======================= rope table =======================
__global__ void rope_tab_kernel(const int* __restrict__ sp) {
    int idx = threadIdx.x;
    int s = idx >> 6, pp = idx & 63;
    double f = (double)(sp[0] + s) * exp(-9.210340371976184 * ((double)pp / 64.0));
    double cd, sd; sincos(f, &sd, &cd);
    g_tab[idx] = make_float2((float)cd, (float)sd);
}

// ======================= fp16 GEMM 128x128, K-split =======================
#define BK  32
#define GAW 20    // Ah stride (words): 16 data + 4 pad; ldsm banks 20l mod 32 distinct
#define GBW 68    // Bh stride (words): 64 data + 4 pad; ldsm banks 4l distinct
#define G16_SMEM_BYTES ((128*GAW + 32*GBW) * 4)

__device__ void gemm16_tile(const float* __restrict__ A, int lda,
                            const float* __restrict__ W, int ldw,
                            float* __restrict__ C, int ldc,
                            int m0, int n0w, int n0c, int kbase, int KT)
{
    extern __shared__ float sm[];
    unsigned* Ah = (unsigned*)sm;
    unsigned* Bh = (unsigned*)sm + 128 * GAW;

    int tid = threadIdx.x, lane = tid & 31, wid = tid >> 5;
    int wm = wid >> 2, wn = wid & 3;         // 2 x 4 warps, warp tile 64x32
    int gr = lane >> 2, kq = lane & 3;

    int arow = tid >> 1, ahalf = tid & 1;    // A: 128 rows x 2 halves (16 floats)
    int brow = tid >> 3, bslot = tid & 7;    // B: 32 k-rows x 8 slots (16 floats)

    unsigned sbase = (unsigned)__cvta_generic_to_shared(sm);
    unsigned a_addr = sbase + (unsigned)(wm * 64 + (lane & 15)) * (GAW * 4) +
                      ((lane >> 4) << 4);
    unsigned b_addr = sbase + (unsigned)(128 * GAW) * 4 +
                      (unsigned)((lane & 7) + (((lane >> 3) & 1) << 3)) * (GBW * 4) +
                      (unsigned)(wn * 64) + ((lane >> 4) << 4);

    float acc[4][4][4];
#pragma unroll
    for (int mt = 0; mt < 4; mt++)
#pragma unroll
        for (int nt = 0; nt < 4; nt++)
#pragma unroll
            for (int i = 0; i < 4; i++) acc[mt][nt][i] = 0.f;

    unsigned pa[8], pb[8];
    auto prefetch = [&](int k0) {
        const float4* ap = (const float4*)(A + (long)(m0 + arow) * lda + k0 + ahalf * 16);
        const float4* bp = (const float4*)(W + (long)(k0 + brow) * ldw + n0w + bslot * 16);
#pragma unroll
        for (int i = 0; i < 4; i++) {
            float4 av = ap[i];
            float4 bv = bp[i];
            pa[2 * i]     = packh2(av.x, av.y);
            pa[2 * i + 1] = packh2(av.z, av.w);
            pb[2 * i]     = packh2(bv.x, bv.y);
            pb[2 * i + 1] = packh2(bv.z, bv.w);
        }
    };

    prefetch(kbase);

    for (int kt = 0; kt < KT; kt++) {
        __syncthreads();   // previous iteration's reads done (no-op cost at entry)
        *(uint4*)&Ah[arow * GAW + ahalf * 8]     = make_uint4(pa[0], pa[1], pa[2], pa[3]);
        *(uint4*)&Ah[arow * GAW + ahalf * 8 + 4] = make_uint4(pa[4], pa[5], pa[6], pa[7]);
        *(uint4*)&Bh[brow * GBW + bslot * 8]     = make_uint4(pb[0], pb[1], pb[2], pb[3]);
        *(uint4*)&Bh[brow * GBW + bslot * 8 + 4] = make_uint4(pb[4], pb[5], pb[6], pb[7]);
        __syncthreads();   // tiles visible

        if (kt + 1 < KT) prefetch(kbase + (kt + 1) * BK);

#pragma unroll
        for (int kb = 0; kb < 2; kb++) {
            unsigned af[4][4];
#pragma unroll
            for (int mt = 0; mt < 4; mt++)
                ldsm4(af[mt][0], af[mt][1], af[mt][2], af[mt][3],
                      a_addr + (unsigned)(mt * 16 * GAW * 4) + kb * 32);
#pragma unroll
            for (int ntp = 0; ntp < 2; ntp++) {
                unsigned b00, b01, b10, b11;
                ldsm4t(b00, b01, b10, b11,
                       b_addr + (unsigned)(kb * 16 * GBW * 4) + ntp * 32);
#pragma unroll
                for (int mt = 0; mt < 4; mt++) {
                    mma16h(acc[mt][2 * ntp],     af[mt][0], af[mt][1], af[mt][2], af[mt][3], b00, b01);
                    mma16h(acc[mt][2 * ntp + 1], af[mt][0], af[mt][1], af[mt][2], af[mt][3], b10, b11);
                }
            }
        }
    }

#pragma unroll
    for (int mt = 0; mt < 4; mt++)
#pragma unroll
        for (int nt = 0; nt < 4; nt++) {
            int row = m0 + wm * 64 + mt * 16 + gr;
            int col = n0c + wn * 32 + nt * 8 + 2 * kq;
            *(float2*)(C + (long)row * ldc + col) =
                make_float2(acc[mt][nt][0], acc[mt][nt][1]);
            *(float2*)(C + (long)(row + 8) * ldc + col) =
                make_float2(acc[mt][nt][2], acc[mt][nt][3]);
        }
}

__global__ void __launch_bounds__(256, 2)
qkv_kernel(const float* __restrict__ x, const float* __restrict__ Wq,
           const float* __restrict__ Wk, const float* __restrict__ Wv) {
    int y = blockIdx.y, z = blockIdx.z;
    const float* W; int ldw, n0w, n0c;
    if (y < 32)      { W = Wq; ldw = 4096; n0w = y * 128;        n0c = y * 128; }
    else if (y < 40) { W = Wk; ldw = 1024; n0w = (y - 32) * 128; n0c = 4096 + (y - 32) * 128; }
    else             { W = Wv; ldw = 1024; n0w = (y - 40) * 128; n0c = 5120 + (y - 40) * 128; }
    gemm16_tile(x, 4096, W, ldw, g_p[z], NC, blockIdx.x * 128, n0w, n0c, z * 1024, 32);
}

__global__ void __launch_bounds__(256, 2)
out_kernel(const float* __restrict__ Wo) {
    int z = blockIdx.z;
    gemm16_tile(g_ctx, 4096, Wo, 4096, g_p[z], 4096,
                blockIdx.x * 128, blockIdx.y * 128, blockIdx.y * 128, z * 1024, 32);
}

// ======================= combines =======================
__global__ void qkv_combine_kernel() {
    int idx = blockIdx.x * 256 + threadIdx.x;
    int row = idx / (NC / 2);
    int p   = idx - row * (NC / 2);
    int col = 2 * p;
    float v0 = 0.f, v1 = 0.f;
#pragma unroll
    for (int h = 0; h < KS; h++) {
        const float* src = g_p[h] + (long)row * NC + col;
        v0 += src[0]; v1 += src[1];
    }
    if (col < 4096) {
        int pp = (col & 127) >> 1;
        float2 cs = g_tab[((row & 15) << 6) + pp];
        const float qs = 0.08838834764831845f * 1.4426950408889634f;
        float t = (v0 * cs.x - v1 * cs.y) * qs;
        v1 = (v0 * cs.y + v1 * cs.x) * qs; v0 = t;
        *(float2*)(g_q + (long)row * 4096 + col) = make_float2(v0, v1);
    } else if (col < 5120) {
        int c2 = col - 4096;
        int pp = (c2 & 127) >> 1;
        float2 cs = g_tab[((row & 15) << 6) + pp];
        float t = v0 * cs.x - v1 * cs.y;
        v1 = v0 * cs.y + v1 * cs.x; v0 = t;
        *(float2*)(g_kn + (long)row * 1024 + c2) = make_float2(v0, v1);
    } else {
        *(float2*)(g_vn + (long)row * 1024 + (col - 5120)) = make_float2(v0, v1);
    }
}

__global__ void out_combine_kernel(float* __restrict__ out) {
    int idx = blockIdx.x * 256 + threadIdx.x;
    float4 a = *(const float4*)(g_p[0] + 4 * (long)idx);
    float4 b = *(const float4*)(g_p[1] + 4 * (long)idx);
    float4 c = *(const float4*)(g_p[2] + 4 * (long)idx);
    float4 d = *(const float4*)(g_p[3] + 4 * (long)idx);
    *(float4*)(out + 4 * (long)idx) =
        make_float4(a.x + b.x + c.x + d.x, a.y + b.y + c.y + d.y,
                    a.z + b.z + c.z + d.z, a.w + b.w + c.w + d.w);
}

// ======================= attention (R14, unchanged) =======================
#define TC   64
#define SSTR 132
#define KW   68
#define VW   68
#define QW   68
#define AOFF_KH  0
#define AOFF_VH  (TC*KW)
#define AOFF_QH  (AOFF_VH + TC*VW)
#define OBS      (TC*SSTR)
#define AOFF_EX  (4*OBS)
#define ATTN_SMEM_BYTES ((AOFF_EX + 512) * 4)

__global__ void __launch_bounds__(512, 1)
attn_kernel(const float* __restrict__ cache_k,
            const float* __restrict__ cache_v,
            const int* __restrict__ sp)
{
    extern __shared__ float sm[];
    unsigned* Kh = (unsigned*)(sm + AOFF_KH);
    unsigned* Vh = (unsigned*)(sm + AOFF_VH);
    unsigned* Qh = (unsigned*)(sm + AOFF_QH);
    float* ex = sm + AOFF_EX;

    int tid = threadIdx.x, lane = tid & 31, wid = tid >> 5;
    int b = blockIdx.x >> 3, kvh = blockIdx.x & 7;
    int start = sp[0], kvlen = start + S_;
    int wm = wid & 3, wn = wid >> 2;
    int gr = lane >> 2, kq = lane & 3;
    int rm = wm * 16;
    int gtid = wm * 32 + lane;

    int tok  = wn * 16 + (gtid >> 3);
    int slot = gtid & 7;

    unsigned sbase = (unsigned)__cvta_generic_to_shared(sm);
    unsigned qa_addr = sbase + AOFF_QH * 4 +
        (unsigned)(rm + (lane & 15)) * (QW * 4) + ((lane >> 4) << 4);
    unsigned kb_addr = sbase + AOFF_KH * 4 +
        (unsigned)(wn * 16 + (lane & 7) + ((lane >> 4) << 3)) * (KW * 4) +
        (((lane >> 3) & 1) << 4);
    unsigned vb_addr = sbase + AOFF_VH * 4 +
        (unsigned)(wn * 16 + (lane & 7) + (((lane >> 3) & 1) << 3)) * (VW * 4) +
        ((lane >> 4) << 4);

    {
        int r = tid >> 3, sl = tid & 7;
        const float* qp = g_q + (long)(b * S_ + (r & 15)) * D_ + (kvh * NREP_ + (r >> 4)) * HD_;
#pragma unroll
        for (int i = 0; i < 8; i++) {
            int w = sl + 8 * i;
            float2 v = *(const float2*)(qp + 2 * w);
            Qh[r * QW + w] = packh2(v.x, v.y);
        }
    }

    float m0r = -1e30f, m1r = -1e30f, l0r = 0.f, l1r = 0.f;
    float cacc[16][4];
#pragma unroll
    for (int nt = 0; nt < 16; nt++)
#pragma unroll
        for (int i = 0; i < 4; i++) cacc[nt][i] = 0.f;

    unsigned kh[8], vh[8];
    auto prefetch = [&](int t0) {
        int t = t0 + tok;
        const float *sk, *sv;
        if (t < start) {
            long o = ((((long)b * MAXS_ + t) * KVH_) + kvh) * HD_;
            sk = cache_k + o; sv = cache_v + o;
        } else {
            int tt = min(t, kvlen - 1);
            long o = (((long)(b * S_ + (tt - start))) * KVH_ + kvh) * HD_;
            sk = g_kn + o; sv = g_vn + o;
        }
        const float4* k4 = (const float4*)(sk + slot * 16);
        const float4* v4 = (const float4*)(sv + slot * 16);
#pragma unroll
        for (int i = 0; i < 4; i++) {
            float4 kv = k4[i];
            float4 vv = v4[i];
            kh[2 * i]     = packh2(kv.x, kv.y);
            kh[2 * i + 1] = packh2(kv.z, kv.w);
            vh[2 * i]     = packh2(vv.x, vv.y);
            vh[2 * i + 1] = packh2(vv.z, vv.w);
        }
    };

    int NCH = (kvlen + TC - 1) / TC;
    prefetch(0);
    __syncthreads();

    for (int j = 0; j < NCH; j++) {
        *(uint4*)&Kh[tok * KW + slot * 8]     = make_uint4(kh[0], kh[1], kh[2], kh[3]);
        *(uint4*)&Kh[tok * KW + slot * 8 + 4] = make_uint4(kh[4], kh[5], kh[6], kh[7]);
        *(uint4*)&Vh[tok * VW + slot * 8]     = make_uint4(vh[0], vh[1], vh[2], vh[3]);
        *(uint4*)&Vh[tok * VW + slot * 8 + 4] = make_uint4(vh[4], vh[5], vh[6], vh[7]);
        GROUP_BAR(1 + wn);

        if (j + 1 < NCH) prefetch((j + 1) * TC);

        float sacc[2][4];
#pragma unroll
        for (int nt = 0; nt < 2; nt++)
#pragma unroll
            for (int i = 0; i < 4; i++) sacc[nt][i] = 0.f;
#pragma unroll
        for (int kb = 0; kb < 8; kb++) {
            unsigned a0, a1, a2, a3, b0, b1, b2, b3;
            ldsm4(a0, a1, a2, a3, qa_addr + kb * 32);
            ldsm4(b0, b1, b2, b3, kb_addr + kb * 32);
            mma16h(sacc[0], a0, a1, a2, a3, b0, b1);
            mma16h(sacc[1], a0, a1, a2, a3, b2, b3);
        }

        if (j == NCH - 1 && (kvlen & (TC - 1))) {
#pragma unroll
            for (int nt = 0; nt < 2; nt++) {
                int tk = j * TC + wn * 16 + nt * 8 + 2 * kq;
                if (tk >= kvlen)     { sacc[nt][0] = -1e30f; sacc[nt][2] = -1e30f; }
                if (tk + 1 >= kvlen) { sacc[nt][1] = -1e30f; sacc[nt][3] = -1e30f; }
            }
        }

        float mw0 = fmaxf(fmaxf(sacc[0][0], sacc[0][1]), fmaxf(sacc[1][0], sacc[1][1]));
        float mw1 = fmaxf(fmaxf(sacc[0][2], sacc[0][3]), fmaxf(sacc[1][2], sacc[1][3]));
        mw0 = fmaxf(mw0, __shfl_xor_sync(0xffffffffu, mw0, 1));
        mw0 = fmaxf(mw0, __shfl_xor_sync(0xffffffffu, mw0, 2));
        mw1 = fmaxf(mw1, __shfl_xor_sync(0xffffffffu, mw1, 1));
        mw1 = fmaxf(mw1, __shfl_xor_sync(0xffffffffu, mw1, 2));
        float M0 = fmaxf(m0r, mw0), M1 = fmaxf(m1r, mw1);
        if (__any_sync(0xffffffffu, (M0 > m0r) | (M1 > m1r))) {
            float sc0 = ex2f(m0r - M0), sc1 = ex2f(m1r - M1);
            l0r *= sc0;  l1r *= sc1;
#pragma unroll
            for (int nt = 0; nt < 16; nt++) {
                cacc[nt][0] *= sc0; cacc[nt][1] *= sc0;
                cacc[nt][2] *= sc1; cacc[nt][3] *= sc1;
            }
            m0r = M0;  m1r = M1;
        }
        float Mb0 = M0 - 8.f, Mb1 = M1 - 8.f;
        float g00 = ex2f(sacc[0][0] - Mb0), g01 = ex2f(sacc[0][1] - Mb0);
        float g02 = ex2f(sacc[0][2] - Mb1), g03 = ex2f(sacc[0][3] - Mb1);
        float h00 = ex2f(sacc[1][0] - Mb0), h01 = ex2f(sacc[1][1] - Mb0);
        float h02 = ex2f(sacc[1][2] - Mb1), h03 = ex2f(sacc[1][3] - Mb1);
        l0r += (g00 + g01) + (h00 + h01);
        l1r += (g02 + g03) + (h02 + h03);
        unsigned pa0 = packh2(g00, g01), pa1 = packh2(g02, g03);
        unsigned pa2 = packh2(h00, h01), pa3 = packh2(h02, h03);

#pragma unroll
        for (int db = 0; db < 8; db++) {
            unsigned b00, b01, b10, b11;
            ldsm4t(b00, b01, b10, b11, vb_addr + db * 32);
            mma16h(cacc[2 * db],     pa0, pa1, pa2, pa3, b00, b01);
            mma16h(cacc[2 * db + 1], pa0, pa1, pa2, pa3, b10, b11);
        }

        GROUP_BAR(1 + wn);
    }

    l0r += __shfl_xor_sync(0xffffffffu, l0r, 1);
    l0r += __shfl_xor_sync(0xffffffffu, l0r, 2);
    l1r += __shfl_xor_sync(0xffffffffu, l1r, 1);
    l1r += __shfl_xor_sync(0xffffffffu, l1r, 2);
    if (kq == 0) { ex[wn * 64 + rm + gr] = m0r; ex[wn * 64 + rm + gr + 8] = m1r; }
    __syncthreads();
    float M0 = -1e30f, M1 = -1e30f;
#pragma unroll
    for (int w = 0; w < 4; w++) {
        M0 = fmaxf(M0, ex[w * 64 + rm + gr]);
        M1 = fmaxf(M1, ex[w * 64 + rm + gr + 8]);
    }
    float sc0 = ex2f(m0r - M0), sc1 = ex2f(m1r - M1);
    if (kq == 0) {
        ex[256 + wn * 64 + rm + gr]     = l0r * sc0;
        ex[256 + wn * 64 + rm + gr + 8] = l1r * sc1;
    }
    float* Ob = sm + wn * OBS;
#pragma unroll
    for (int nt = 0; nt < 16; nt++) {
        int d = nt * 8 + 2 * kq;
        *(float2*)&Ob[(rm + gr) * SSTR + d] =
            make_float2(cacc[nt][0] * sc0, cacc[nt][1] * sc0);
        *(float2*)&Ob[(rm + gr + 8) * SSTR + d] =
            make_float2(cacc[nt][2] * sc1, cacc[nt][3] * sc1);
    }
    __syncthreads();
#pragma unroll
    for (int i = 0; i < 4; i++) {
        int f = i * 512 + tid;
        int r = f >> 5, d4 = f & 31;
        float4 s0 = *(const float4*)&sm[0 * OBS + r * SSTR + d4 * 4];
        float4 s1 = *(const float4*)&sm[1 * OBS + r * SSTR + d4 * 4];
        float4 s2 = *(const float4*)&sm[2 * OBS + r * SSTR + d4 * 4];
        float4 s3 = *(const float4*)&sm[3 * OBS + r * SSTR + d4 * 4];
        float L = ex[256 + r] + ex[256 + 64 + r] + ex[256 + 128 + r] + ex[256 + 192 + r];
        float inv = 1.f / L;
        float4 o = make_float4((s0.x + s1.x + s2.x + s3.x) * inv,
                               (s0.y + s1.y + s2.y + s3.y) * inv,
                               (s0.z + s1.z + s2.z + s3.z) * inv,
                               (s0.w + s1.w + s2.w + s3.w) * inv);
        *(float4*)(g_ctx + (long)(b * S_ + (r & 15)) * D_ +
                   (kvh * NREP_ + (r >> 4)) * HD_ + d4 * 4) = o;
    }
}

// ======================= launch =======================
extern "C" void kernel_launch(void* const* d_in, const int* in_sizes, int n_in,
                              void* d_out, int out_size) {
    const float* x       = (const float*)d_in[0];
    const float* Wq      = (const float*)d_in[1];
    const float* Wk      = (const float*)d_in[2];
    const float* Wv      = (const float*)d_in[3];
    const float* Wo      = (const float*)d_in[4];
    const float* cache_k = (const float*)d_in[5];
    const float* cache_v = (const float*)d_in[6];
    const int*   sp      = (const int*)d_in[7];
    float* out = (float*)d_out;

    cudaFuncSetAttribute(qkv_kernel,  cudaFuncAttributeMaxDynamicSharedMemorySize, G16_SMEM_BYTES);
    cudaFuncSetAttribute(out_kernel,  cudaFuncAttributeMaxDynamicSharedMemorySize, G16_SMEM_BYTES);
    cudaFuncSetAttribute(attn_kernel, cudaFuncAttributeMaxDynamicSharedMemorySize, ATTN_SMEM_BYTES);

    rope_tab_kernel<<<1, 1024>>>(sp);
    qkv_kernel<<<dim3(2, 48, KS), 256, G16_SMEM_BYTES>>>(x, Wq, Wk, Wv);
    qkv_combine_kernel<<<(MROWS * NC / 2) / 256, 256>>>();
    attn_kernel<<<128, 512, ATTN_SMEM_BYTES>>>(cache_k, cache_v, sp);
    out_kernel<<<dim3(2, 32, KS), 256, G16_SMEM_BYTES>>>(Wo);
    out_combine_kernel<<<(MROWS * D_ / 4) / 256, 256>>>(out);
}